// round 12
// baseline (speedup 1.0000x reference)
#include <cuda_runtime.h>
#include <cuda_fp16.h>
#include <math.h>
#include <stdint.h>

#define Bn   2
#define Sn   4096
#define Hn   1024
#define Mn   (Bn * Sn)       // 8192 rows
#define WIN  32

// ---------------- scratch (no allocations allowed) ----------------
// fp16 pair buffers (u32 = two fp16, even k in low half)
__device__ uint32_t g_x_h  [Mn * Hn / 2];
__device__ uint32_t g_wq_h [Hn * Hn / 2];
__device__ uint32_t g_wk_h [Hn * Hn / 2];
__device__ uint32_t g_wv_h [Hn * Hn / 2];
__device__ uint32_t g_wo_h [Hn * Hn / 2];
__device__ uint32_t g_w1_h [(Hn / 2) * Hn / 2];
__device__ uint32_t g_w2_h [Hn * (Hn / 2) / 2];
__device__ uint32_t g_q_h  [Mn * Hn / 2];
__device__ uint32_t g_k_h  [Mn * Hn / 2];
__device__ uint32_t g_v_h  [Mn * Hn / 2];
__device__ uint32_t g_at_h [Mn * Hn / 2];
__device__ uint32_t g_ln_h [Mn * Hn / 2];
__device__ uint32_t g_h1_h [Mn * Hn / 4];
__device__ float g_drft[Mn * Hn];
__device__ float g_psc [4 * Mn * 32];
__device__ float g_prob[Mn * 32];

// ---------------- fp16 helpers ----------------
__device__ __forceinline__ uint32_t pack2_h(__half a, __half b) {
    __half2 t; t.x = a; t.y = b;
    return *(uint32_t*)&t;
}
__device__ __forceinline__ uint32_t hi2h(float x, float y) {
    return pack2_h(__float2half_rn(x), __float2half_rn(y));
}
__device__ __forceinline__ float2 h2f2(uint32_t u) {
    __half2 h = *(__half2*)&u;
    return __half22float2(h);
}
__device__ __forceinline__ void mma_f16(float c[4], const uint32_t a[4], uint32_t b0, uint32_t b1) {
    asm("mma.sync.aligned.m16n8k16.row.col.f32.f16.f16.f32 "
        "{%0,%1,%2,%3}, {%4,%5,%6,%7}, {%8,%9}, {%0,%1,%2,%3};\n"
        : "+f"(c[0]), "+f"(c[1]), "+f"(c[2]), "+f"(c[3])
        : "r"(a[0]), "r"(a[1]), "r"(a[2]), "r"(a[3]), "r"(b0), "r"(b1));
}
__device__ __forceinline__ void ldmx4(uint32_t r[4], const uint32_t* p) {
    uint32_t a = (uint32_t)__cvta_generic_to_shared(p);
    asm volatile("ldmatrix.sync.aligned.m8n8.x4.shared.b16 {%0,%1,%2,%3}, [%4];"
        : "=r"(r[0]), "=r"(r[1]), "=r"(r[2]), "=r"(r[3]) : "r"(a));
}
__device__ __forceinline__ void cp16(uint32_t sdst, const void* gsrc) {
    asm volatile("cp.async.cg.shared.global [%0], [%1], 16;" :: "r"(sdst), "l"(gsrc));
}
#define CP_COMMIT() asm volatile("cp.async.commit_group;" ::: "memory")

// ---------------- conversion: fp32 -> fp16 pairs ----------------
__global__ __launch_bounds__(256) void conv_hi(
    const float* __restrict__ in, uint32_t* __restrict__ hi, int n4)
{
    int i = blockIdx.x * 256 + threadIdx.x;
    if (i >= n4) return;
    float4 v = ((const float4*)in)[i];
    ((uint2*)hi)[i] = make_uint2(hi2h(v.x, v.y), hi2h(v.z, v.w));
}

// ---------------- GEMM: C[M,N] = A[M,K] @ B[N,K]^T, fp16, 3-stage cp.async ----------------
// EPI 0: fp32 plain     EPI 1: fp32 += aux1
// EPI 2: fp16-pair out = gelu(acc + aux2[n])    EPI 3: fp32 = aux1 + acc + aux2[n]
// EPI 4: fp16-pair plain
#define BM 128
#define BN 128
#define SLD 20                         // u32 row stride (16 used + 4 pad)
#define MATW (BM * SLD)                // u32 per matrix tile (2560)
#define STGW (2 * MATW)                // u32 per stage (Ah, Bh)
#define NSTAGE 3
#define GEMM_SMEM (NSTAGE * STGW * 4)  // bytes (61440)

template<int EPI>
__global__ __launch_bounds__(256, 2) void gemm_mma(
    const uint32_t* __restrict__ Ahg, const uint32_t* __restrict__ Bhg,
    float* __restrict__ C, uint32_t* __restrict__ Chi,
    int M, int N, int K,
    const float* __restrict__ aux1, const float* __restrict__ aux2)
{
    extern __shared__ uint32_t smem[];

    const int Kd2  = K >> 1;
    const int nt   = Kd2 >> 4;          // k-tiles of 16 u32 (32 elements)
    const int tid  = threadIdx.x;
    const int wid  = tid >> 5;
    const int lane = tid & 31;
    const int g    = lane >> 2;
    const int tq   = lane & 3;

    const int bm = blockIdx.y * BM;
    const int bn = blockIdx.x * BN;
    const int m0 = (wid & 3) * 32;
    const int n0 = (wid >> 2) * 64;

    const int sr0 = tid >> 2,         sc0 = (tid & 3) << 2;
    const int sr1 = (tid + 256) >> 2, sc1 = ((tid + 256) & 3) << 2;
    const uint32_t smem_base = (uint32_t)__cvta_generic_to_shared(smem);

    float acc[2][8][4];
#pragma unroll
    for (int i = 0; i < 2; i++)
#pragma unroll
        for (int j = 0; j < 8; j++)
#pragma unroll
            for (int r = 0; r < 4; r++) acc[i][j][r] = 0.f;

    const int ar  = m0 + ((lane & 15) >> 3) * 8 + (lane & 7);
    const int ac4 = (lane >> 4) * 4;
    const int br  = n0 + (lane >> 4) * 8 + (lane & 7);
    const int bc4 = ((lane & 15) >> 3) * 4;

    auto stage = [&](int k, int b) {
        const uint32_t sbase = smem_base + (uint32_t)(b * STGW) * 4u;
        const int koff = k * 16;
        {
            const size_t ga = (size_t)(bm + sr0) * Kd2 + koff + sc0;
            const size_t gb = (size_t)(bn + sr0) * Kd2 + koff + sc0;
            const uint32_t so = (uint32_t)(sr0 * SLD + sc0) * 4u;
            cp16(sbase + 0 * MATW * 4 + so, Ahg + ga);
            cp16(sbase + 1 * MATW * 4 + so, Bhg + gb);
        }
        {
            const size_t ga = (size_t)(bm + sr1) * Kd2 + koff + sc1;
            const size_t gb = (size_t)(bn + sr1) * Kd2 + koff + sc1;
            const uint32_t so = (uint32_t)(sr1 * SLD + sc1) * 4u;
            cp16(sbase + 0 * MATW * 4 + so, Ahg + ga);
            cp16(sbase + 1 * MATW * 4 + so, Bhg + gb);
        }
    };

    stage(0, 0);
    CP_COMMIT();
    if (nt > 1) { stage(1, 1); CP_COMMIT(); }

    int b = 0;
    for (int k = 0; k < nt; k++) {
        if (k + 2 < nt) {
            int bs = b + 2; if (bs >= NSTAGE) bs -= NSTAGE;
            stage(k + 2, bs);
            CP_COMMIT();
            asm volatile("cp.async.wait_group 2;" ::: "memory");
        } else if (k + 1 < nt) {
            asm volatile("cp.async.wait_group 1;" ::: "memory");
        } else {
            asm volatile("cp.async.wait_group 0;" ::: "memory");
        }
        __syncthreads();

        const uint32_t* sAh = smem + b * STGW + 0 * MATW;
        const uint32_t* sBh = smem + b * STGW + 1 * MATW;

#pragma unroll
        for (int kc = 0; kc < 16; kc += 8) {
            uint32_t ah[2][4];
            ldmx4(ah[0], sAh + (ar     ) * SLD + kc + ac4);
            ldmx4(ah[1], sAh + (ar + 16) * SLD + kc + ac4);
#pragma unroll
            for (int h = 0; h < 2; h++) {
                uint32_t bh0[4], bh1[4];
                ldmx4(bh0, sBh + (br + (2 * h)     * 16) * SLD + kc + bc4);
                ldmx4(bh1, sBh + (br + (2 * h + 1) * 16) * SLD + kc + bc4);
                const int p0 = 4 * h, p1 = 4 * h + 2;
                mma_f16(acc[0][p0],     ah[0], bh0[0], bh0[1]);
                mma_f16(acc[0][p0 + 1], ah[0], bh0[2], bh0[3]);
                mma_f16(acc[1][p0],     ah[1], bh0[0], bh0[1]);
                mma_f16(acc[1][p0 + 1], ah[1], bh0[2], bh0[3]);
                mma_f16(acc[0][p1],     ah[0], bh1[0], bh1[1]);
                mma_f16(acc[0][p1 + 1], ah[0], bh1[2], bh1[3]);
                mma_f16(acc[1][p1],     ah[1], bh1[0], bh1[1]);
                mma_f16(acc[1][p1 + 1], ah[1], bh1[2], bh1[3]);
            }
        }
        __syncthreads();
        if (++b >= NSTAGE) b = 0;
    }

    // ---- epilogue: frag (mf,nf) -> rows (g, g+8), cols nf*8 + tq*2 (+1) ----
#pragma unroll
    for (int mf = 0; mf < 2; mf++) {
#pragma unroll
        for (int nf = 0; nf < 8; nf++) {
            const int r0 = bm + m0 + mf * 16 + g;
            const int r1 = r0 + 8;
            const int cc = bn + n0 + nf * 8 + tq * 2;
            float v0 = acc[mf][nf][0], v1 = acc[mf][nf][1];
            float v2 = acc[mf][nf][2], v3 = acc[mf][nf][3];

            if (EPI == 1 || EPI == 3) {
                const float2 a0 = *(const float2*)(aux1 + (size_t)r0 * N + cc);
                const float2 a1 = *(const float2*)(aux1 + (size_t)r1 * N + cc);
                v0 += a0.x; v1 += a0.y; v2 += a1.x; v3 += a1.y;
            }
            if (EPI == 2 || EPI == 3) {
                const float2 bb = *(const float2*)(aux2 + cc);
                v0 += bb.x; v1 += bb.y; v2 += bb.x; v3 += bb.y;
            }
            if (EPI == 2) {
                v0 *= normcdff(v0); v1 *= normcdff(v1);
                v2 *= normcdff(v2); v3 *= normcdff(v3);
            }
            if (EPI == 2 || EPI == 4) {
                const int Nd2 = N >> 1;
                Chi[(size_t)r0 * Nd2 + (cc >> 1)] = hi2h(v0, v1);
                Chi[(size_t)r1 * Nd2 + (cc >> 1)] = hi2h(v2, v3);
            } else {
                *(float2*)(C + (size_t)r0 * N + cc) = make_float2(v0, v1);
                *(float2*)(C + (size_t)r1 * N + cc) = make_float2(v2, v3);
            }
        }
    }
}

// ---------------- attention: scores (H-split partials, fp16 Q/K in gmem) ----------------
#define CH 64

__global__ __launch_bounds__(256) void attn_scores(
    const uint32_t* __restrict__ Qh, const uint32_t* __restrict__ Kh, float* __restrict__ psc)
{
    __shared__ float Ks[63][CH + 1];
    __shared__ float Qs[32][CH + 1];

    const int tid = threadIdx.x;
    const int q0  = blockIdx.x * 32;
    const int b   = blockIdx.y;
    const int hs  = blockIdx.z;
    const int ti  = tid >> 3;
    const int wg  = tid & 7;
    const int Hd2 = Hn / 2;

    float acc[4] = {0.f, 0.f, 0.f, 0.f};

    for (int h0 = hs * 256; h0 < hs * 256 + 256; h0 += CH) {
        // K: 63 rows x 64 elems = 63*16 uint2 units (4 elems each)
        for (int idx = tid; idx < 63 * 16; idx += 256) {
            int r  = idx >> 4;
            int c  = (idx & 15) << 2;
            int jb = q0 - 31 + r;
            uint2 u = make_uint2(0u, 0u);
            if (jb >= 0)
                u = *(const uint2*)(Kh + (size_t)(b * Sn + jb) * Hd2 + ((h0 + c) >> 1));
            float2 f0 = h2f2(u.x), f1 = h2f2(u.y);
            Ks[r][c] = f0.x; Ks[r][c + 1] = f0.y; Ks[r][c + 2] = f1.x; Ks[r][c + 3] = f1.y;
        }
        for (int idx = tid; idx < 32 * 16; idx += 256) {
            int r = idx >> 4;
            int c = (idx & 15) << 2;
            uint2 u = *(const uint2*)(Qh + (size_t)(b * Sn + q0 + r) * Hd2 + ((h0 + c) >> 1));
            float2 f0 = h2f2(u.x), f1 = h2f2(u.y);
            Qs[r][c] = f0.x; Qs[r][c + 1] = f0.y; Qs[r][c + 2] = f1.x; Qs[r][c + 3] = f1.y;
        }
        __syncthreads();
#pragma unroll 8
        for (int kk = 0; kk < CH; kk++) {
            float qv = Qs[ti][kk];
#pragma unroll
            for (int j = 0; j < 4; j++)
                acc[j] += qv * Ks[ti + wg * 4 + j][kk];
        }
        __syncthreads();
    }
    const size_t base = ((size_t)hs * Mn + b * Sn + q0 + ti) * 32 + wg * 4;
#pragma unroll
    for (int j = 0; j < 4; j++) psc[base + j] = acc[j];
}

// ---------------- attention: softmax ----------------
__global__ __launch_bounds__(256) void attn_softmax(
    const float* __restrict__ psc, float* __restrict__ prob)
{
    const int warp = threadIdx.x >> 5, lane = threadIdx.x & 31;
    const int row  = blockIdx.x * 8 + warp;
    const int iq   = row & (Sn - 1);
    int wmin = 31 - iq; if (wmin < 0) wmin = 0;

    float s = 0.f;
#pragma unroll
    for (int hs = 0; hs < 4; hs++)
        s += psc[((size_t)hs * Mn + row) * 32 + lane];
    s *= (1.0f / 32.0f);

    const bool valid = (lane >= wmin);
    float m = valid ? s : -1e30f;
#pragma unroll
    for (int o = 16; o; o >>= 1) m = fmaxf(m, __shfl_xor_sync(0xffffffffu, m, o));
    float p = valid ? expf(s - m) : 0.f;
    float sum = p;
#pragma unroll
    for (int o = 16; o; o >>= 1) sum += __shfl_xor_sync(0xffffffffu, sum, o);
    prob[(size_t)row * 32 + lane] = p / sum;
}

// ---------------- attention: PV (fp16 V in gmem), emits fp16 pairs ----------------
__global__ __launch_bounds__(256) void attn_pv(
    const uint32_t* __restrict__ Vh, const float* __restrict__ prob,
    uint32_t* __restrict__ Ohi)
{
    __shared__ float Vs[63][132];

    const int tid = threadIdx.x;
    const int q0  = blockIdx.x * 32;
    const int b   = blockIdx.y;
    const int h0  = blockIdx.z * 128;
    const int ti  = tid >> 3;
    const int hg  = tid & 7;
    const int Hd2 = Hn / 2;

    // 63 rows x 128 elems = 63*32 uint2 units
    for (int idx = tid; idx < 63 * 32; idx += 256) {
        int r  = idx >> 5;
        int c  = (idx & 31) << 2;
        int jb = q0 - 31 + r;
        uint2 u = make_uint2(0u, 0u);
        if (jb >= 0)
            u = *(const uint2*)(Vh + (size_t)(b * Sn + jb) * Hd2 + ((h0 + c) >> 1));
        float2 f0 = h2f2(u.x), f1 = h2f2(u.y);
        Vs[r][c] = f0.x; Vs[r][c + 1] = f0.y; Vs[r][c + 2] = f1.x; Vs[r][c + 3] = f1.y;
    }
    float p[32];
    const float* pr = prob + (size_t)(b * Sn + q0 + ti) * 32;
#pragma unroll
    for (int w = 0; w < 32; w++) p[w] = pr[w];
    __syncthreads();

    float o[16];
#pragma unroll
    for (int c = 0; c < 16; c++) o[c] = 0.f;
#pragma unroll
    for (int w = 0; w < 32; w++) {
        const float pv = p[w];
        const float* vr = &Vs[ti + w][hg * 16];
#pragma unroll
        for (int c = 0; c < 16; c++) o[c] += pv * vr[c];
    }
    const size_t rowbase = (size_t)(b * Sn + q0 + ti) * Hd2 + (h0 >> 1) + hg * 8;
#pragma unroll
    for (int c = 0; c < 16; c += 2)
        Ohi[rowbase + (c >> 1)] = hi2h(o[c], o[c + 1]);
}

// ---------------- layernorm: single-pass, fp32 in, fp16-pair out ----------------
// 256 threads x 4 contiguous floats = 1024 = Hn; stats + normalize from registers
__global__ __launch_bounds__(256) void ln_kernel(
    const float* __restrict__ X, const float* __restrict__ w,
    const float* __restrict__ bb, uint32_t* __restrict__ Yhi)
{
    const int row = blockIdx.x;
    const int tid = threadIdx.x;
    const float4 v = *(const float4*)(X + (size_t)row * Hn + tid * 4);

    float s  = v.x + v.y + v.z + v.w;
    float ss = v.x * v.x + v.y * v.y + v.z * v.z + v.w * v.w;

    __shared__ float red[64];
#pragma unroll
    for (int o = 16; o; o >>= 1) {
        s  += __shfl_down_sync(0xffffffffu, s,  o);
        ss += __shfl_down_sync(0xffffffffu, ss, o);
    }
    const int warp = tid >> 5, lane = tid & 31;
    if (lane == 0) { red[warp] = s; red[32 + warp] = ss; }
    __syncthreads();
    if (tid == 0) {
        float S = 0.f, SS = 0.f;
        for (int i = 0; i < 8; i++) { S += red[i]; SS += red[32 + i]; }
        red[0] = S; red[1] = SS;
    }
    __syncthreads();
    const float mu   = red[0] * (1.0f / Hn);
    const float var  = red[1] * (1.0f / Hn) - mu * mu;
    const float rstd = rsqrtf(var + 1e-5f);

    const float4 wv = *(const float4*)(w  + tid * 4);
    const float4 bv = *(const float4*)(bb + tid * 4);
    float y0 = (v.x - mu) * rstd * wv.x + bv.x;
    float y1 = (v.y - mu) * rstd * wv.y + bv.y;
    float y2 = (v.z - mu) * rstd * wv.z + bv.z;
    float y3 = (v.w - mu) * rstd * wv.w + bv.w;
    *(uint2*)(Yhi + (size_t)row * (Hn / 2) + tid * 2) = make_uint2(hi2h(y0, y1), hi2h(y2, y3));
}

// ---------------- launch ----------------
extern "C" void kernel_launch(void* const* d_in, const int* in_sizes, int n_in,
                              void* d_out, int out_size)
{
    const float* x   = (const float*)d_in[0];
    const float* Wq  = (const float*)d_in[1];
    const float* Wk  = (const float*)d_in[2];
    const float* Wv  = (const float*)d_in[3];
    const float* Wo  = (const float*)d_in[4];
    const float* lnw = (const float*)d_in[5];
    const float* lnb = (const float*)d_in[6];
    const float* W1  = (const float*)d_in[7];
    const float* b1  = (const float*)d_in[8];
    const float* W2  = (const float*)d_in[9];
    const float* b2  = (const float*)d_in[10];
    float* out = (float*)d_out;

    uint32_t *xh, *wqh, *wkh, *wvh, *woh, *w1h, *w2h;
    uint32_t *qh, *kh, *vh, *ath, *lnh, *h1h;
    float *drft, *psc, *prob;
    cudaGetSymbolAddress((void**)&xh,  g_x_h);
    cudaGetSymbolAddress((void**)&wqh, g_wq_h);
    cudaGetSymbolAddress((void**)&wkh, g_wk_h);
    cudaGetSymbolAddress((void**)&wvh, g_wv_h);
    cudaGetSymbolAddress((void**)&woh, g_wo_h);
    cudaGetSymbolAddress((void**)&w1h, g_w1_h);
    cudaGetSymbolAddress((void**)&w2h, g_w2_h);
    cudaGetSymbolAddress((void**)&qh,  g_q_h);
    cudaGetSymbolAddress((void**)&kh,  g_k_h);
    cudaGetSymbolAddress((void**)&vh,  g_v_h);
    cudaGetSymbolAddress((void**)&ath, g_at_h);
    cudaGetSymbolAddress((void**)&lnh, g_ln_h);
    cudaGetSymbolAddress((void**)&h1h, g_h1_h);
    cudaGetSymbolAddress((void**)&drft, g_drft);
    cudaGetSymbolAddress((void**)&psc,  g_psc);
    cudaGetSymbolAddress((void**)&prob, g_prob);

    cudaFuncSetAttribute(gemm_mma<1>, cudaFuncAttributeMaxDynamicSharedMemorySize, GEMM_SMEM);
    cudaFuncSetAttribute(gemm_mma<2>, cudaFuncAttributeMaxDynamicSharedMemorySize, GEMM_SMEM);
    cudaFuncSetAttribute(gemm_mma<3>, cudaFuncAttributeMaxDynamicSharedMemorySize, GEMM_SMEM);
    cudaFuncSetAttribute(gemm_mma<4>, cudaFuncAttributeMaxDynamicSharedMemorySize, GEMM_SMEM);

    // conversions (fp16 pairs, once per tensor)
    conv_hi<<<(Mn * Hn / 4) / 256, 256>>>(x,  xh,  Mn * Hn / 4);
    conv_hi<<<(Hn * Hn / 4) / 256, 256>>>(Wq, wqh, Hn * Hn / 4);
    conv_hi<<<(Hn * Hn / 4) / 256, 256>>>(Wk, wkh, Hn * Hn / 4);
    conv_hi<<<(Hn * Hn / 4) / 256, 256>>>(Wv, wvh, Hn * Hn / 4);
    conv_hi<<<(Hn * Hn / 4) / 256, 256>>>(Wo, woh, Hn * Hn / 4);
    conv_hi<<<(Hn * Hn / 8) / 256, 256>>>(W1, w1h, Hn * Hn / 8);
    conv_hi<<<(Hn * Hn / 8) / 256, 256>>>(W2, w2h, Hn * Hn / 8);

    dim3 gridH (Hn / BN,       Mn / BM);   // (8, 64)
    dim3 gridH2((Hn / 2) / BN, Mn / BM);   // (4, 64)

    // q, k, v projections -> fp16 pairs
    gemm_mma<4><<<gridH, 256, GEMM_SMEM>>>(xh, wqh, nullptr, qh, Mn, Hn, Hn, nullptr, nullptr);
    gemm_mma<4><<<gridH, 256, GEMM_SMEM>>>(xh, wkh, nullptr, kh, Mn, Hn, Hn, nullptr, nullptr);
    gemm_mma<4><<<gridH, 256, GEMM_SMEM>>>(xh, wvh, nullptr, vh, Mn, Hn, Hn, nullptr, nullptr);

    // banded attention (fp16 Q/K/V)
    attn_scores <<<dim3(Sn / 32, Bn, 4), 256>>>(qh, kh, psc);
    attn_softmax<<<Mn / 8, 256>>>(psc, prob);
    attn_pv     <<<dim3(Sn / 32, Bn, 8), 256>>>(vh, prob, ath);

    // draft = x + attn @ Wo^T  (fp32 out)
    gemm_mma<1><<<gridH, 256, GEMM_SMEM>>>(ath, woh, drft, nullptr, Mn, Hn, Hn, x, nullptr);

    // layernorm -> fp16 pairs (single pass)
    ln_kernel<<<Mn, 256>>>(drft, lnw, lnb, lnh);

    // h1 = gelu(ln @ W1^T + b1) -> fp16 pairs
    gemm_mma<2><<<gridH2, 256, GEMM_SMEM>>>(lnh, w1h, nullptr, h1h, Mn, Hn / 2, Hn, nullptr, b1);

    // out = draft + h1 @ W2^T + b2  (fp32)
    gemm_mma<3><<<gridH, 256, GEMM_SMEM>>>(h1h, w2h, out, nullptr, Mn, Hn, Hn / 2, drft, b2);
}

// round 13
// speedup vs baseline: 1.0856x; 1.0856x over previous
#include <cuda_runtime.h>
#include <cuda_fp16.h>
#include <math.h>
#include <stdint.h>

#define Bn   2
#define Sn   4096
#define Hn   1024
#define Mn   (Bn * Sn)       // 8192 rows
#define WIN  32

// ---------------- scratch (no allocations allowed) ----------------
// fp16 pair buffers (u32 = two fp16, even k in low half)
__device__ uint32_t g_x_h   [Mn * Hn / 2];
__device__ uint32_t g_wqkv_h[3 * Hn * Hn / 2];   // rows: [Wq(1024) | Wk(1024) | Wv(1024)]
__device__ uint32_t g_wo_h  [Hn * Hn / 2];
__device__ uint32_t g_w1_h  [(Hn / 2) * Hn / 2];
__device__ uint32_t g_w2_h  [Hn * (Hn / 2) / 2];
__device__ uint32_t g_qkv_h [Mn * 3 * Hn / 2];   // per row: [q(512u32) | k(512) | v(512)]
__device__ uint32_t g_at_h  [Mn * Hn / 2];
__device__ uint32_t g_ln_h  [Mn * Hn / 2];
__device__ uint32_t g_h1_h  [Mn * Hn / 4];
__device__ float g_drft[Mn * Hn];
__device__ float g_psc [4 * Mn * 32];
__device__ float g_prob[Mn * 32];

#define QKV_LD (3 * Hn / 2)   // 1536 u32 per row
#define KOFF   (Hn / 2)       // 512
#define VOFF   (Hn)           // 1024

// ---------------- fp16 helpers ----------------
__device__ __forceinline__ uint32_t pack2_h(__half a, __half b) {
    __half2 t; t.x = a; t.y = b;
    return *(uint32_t*)&t;
}
__device__ __forceinline__ uint32_t hi2h(float x, float y) {
    return pack2_h(__float2half_rn(x), __float2half_rn(y));
}
__device__ __forceinline__ float2 h2f2(uint32_t u) {
    __half2 h = *(__half2*)&u;
    return __half22float2(h);
}
__device__ __forceinline__ void mma_f16(float c[4], const uint32_t a[4], uint32_t b0, uint32_t b1) {
    asm("mma.sync.aligned.m16n8k16.row.col.f32.f16.f16.f32 "
        "{%0,%1,%2,%3}, {%4,%5,%6,%7}, {%8,%9}, {%0,%1,%2,%3};\n"
        : "+f"(c[0]), "+f"(c[1]), "+f"(c[2]), "+f"(c[3])
        : "r"(a[0]), "r"(a[1]), "r"(a[2]), "r"(a[3]), "r"(b0), "r"(b1));
}
__device__ __forceinline__ void ldmx4(uint32_t r[4], const uint32_t* p) {
    uint32_t a = (uint32_t)__cvta_generic_to_shared(p);
    asm volatile("ldmatrix.sync.aligned.m8n8.x4.shared.b16 {%0,%1,%2,%3}, [%4];"
        : "=r"(r[0]), "=r"(r[1]), "=r"(r[2]), "=r"(r[3]) : "r"(a));
}
__device__ __forceinline__ void cp16(uint32_t sdst, const void* gsrc) {
    asm volatile("cp.async.cg.shared.global [%0], [%1], 16;" :: "r"(sdst), "l"(gsrc));
}
#define CP_COMMIT() asm volatile("cp.async.commit_group;" ::: "memory")

// ---------------- fused conversion: all tensors -> fp16 pairs in one launch ----------------
__global__ __launch_bounds__(256) void conv_all(
    const float* s0, uint32_t* d0, int n0,   // x
    const float* s1, uint32_t* d1, int n1,   // Wq -> wqkv rows 0..1023
    const float* s2, uint32_t* d2, int n2,   // Wk -> wqkv rows 1024..2047
    const float* s3, uint32_t* d3, int n3,   // Wv -> wqkv rows 2048..3071
    const float* s4, uint32_t* d4, int n4c,  // Wo
    const float* s5, uint32_t* d5, int n5,   // W1
    const float* s6, uint32_t* d6, int n6)   // W2
{
    int i = blockIdx.x * 256 + threadIdx.x;
    const float* s; uint32_t* d;
    if      (i < n0)                        { s = s0; d = d0; }
    else if ((i -= n0) < n1)                { s = s1; d = d1; }
    else if ((i -= n1) < n2)                { s = s2; d = d2; }
    else if ((i -= n2) < n3)                { s = s3; d = d3; }
    else if ((i -= n3) < n4c)               { s = s4; d = d4; }
    else if ((i -= n4c) < n5)               { s = s5; d = d5; }
    else if ((i -= n5) < n6)                { s = s6; d = d6; }
    else return;
    float4 v = ((const float4*)s)[i];
    ((uint2*)d)[i] = make_uint2(hi2h(v.x, v.y), hi2h(v.z, v.w));
}

// ---------------- GEMM: C[M,N] = A[M,K] @ B[N,K]^T, fp16, 3-stage cp.async ----------------
// EPI 0: fp32 plain     EPI 1: fp32 += aux1
// EPI 2: fp16-pair out = gelu(acc + aux2[n])    EPI 3: fp32 = aux1 + acc + aux2[n]
// EPI 4: fp16-pair plain
#define BM 128
#define BN 128
#define SLD 20                         // u32 row stride (16 used + 4 pad)
#define MATW (BM * SLD)                // u32 per matrix tile (2560)
#define STGW (2 * MATW)                // u32 per stage (Ah, Bh)
#define NSTAGE 3
#define GEMM_SMEM (NSTAGE * STGW * 4)  // bytes (61440)

template<int EPI>
__global__ __launch_bounds__(256, 2) void gemm_mma(
    const uint32_t* __restrict__ Ahg, const uint32_t* __restrict__ Bhg,
    float* __restrict__ C, uint32_t* __restrict__ Chi,
    int M, int N, int K,
    const float* __restrict__ aux1, const float* __restrict__ aux2)
{
    extern __shared__ uint32_t smem[];

    const int Kd2  = K >> 1;
    const int nt   = Kd2 >> 4;          // k-tiles of 16 u32 (32 elements)
    const int tid  = threadIdx.x;
    const int wid  = tid >> 5;
    const int lane = tid & 31;
    const int g    = lane >> 2;
    const int tq   = lane & 3;

    const int bm = blockIdx.y * BM;
    const int bn = blockIdx.x * BN;
    const int m0 = (wid & 3) * 32;
    const int n0 = (wid >> 2) * 64;

    const int sr0 = tid >> 2,         sc0 = (tid & 3) << 2;
    const int sr1 = (tid + 256) >> 2, sc1 = ((tid + 256) & 3) << 2;
    const uint32_t smem_base = (uint32_t)__cvta_generic_to_shared(smem);

    float acc[2][8][4];
#pragma unroll
    for (int i = 0; i < 2; i++)
#pragma unroll
        for (int j = 0; j < 8; j++)
#pragma unroll
            for (int r = 0; r < 4; r++) acc[i][j][r] = 0.f;

    const int ar  = m0 + ((lane & 15) >> 3) * 8 + (lane & 7);
    const int ac4 = (lane >> 4) * 4;
    const int br  = n0 + (lane >> 4) * 8 + (lane & 7);
    const int bc4 = ((lane & 15) >> 3) * 4;

    auto stage = [&](int k, int b) {
        const uint32_t sbase = smem_base + (uint32_t)(b * STGW) * 4u;
        const int koff = k * 16;
        {
            const size_t ga = (size_t)(bm + sr0) * Kd2 + koff + sc0;
            const size_t gb = (size_t)(bn + sr0) * Kd2 + koff + sc0;
            const uint32_t so = (uint32_t)(sr0 * SLD + sc0) * 4u;
            cp16(sbase + 0 * MATW * 4 + so, Ahg + ga);
            cp16(sbase + 1 * MATW * 4 + so, Bhg + gb);
        }
        {
            const size_t ga = (size_t)(bm + sr1) * Kd2 + koff + sc1;
            const size_t gb = (size_t)(bn + sr1) * Kd2 + koff + sc1;
            const uint32_t so = (uint32_t)(sr1 * SLD + sc1) * 4u;
            cp16(sbase + 0 * MATW * 4 + so, Ahg + ga);
            cp16(sbase + 1 * MATW * 4 + so, Bhg + gb);
        }
    };

    stage(0, 0);
    CP_COMMIT();
    if (nt > 1) { stage(1, 1); CP_COMMIT(); }

    int b = 0;
    for (int k = 0; k < nt; k++) {
        if (k + 2 < nt) {
            int bs = b + 2; if (bs >= NSTAGE) bs -= NSTAGE;
            stage(k + 2, bs);
            CP_COMMIT();
            asm volatile("cp.async.wait_group 2;" ::: "memory");
        } else if (k + 1 < nt) {
            asm volatile("cp.async.wait_group 1;" ::: "memory");
        } else {
            asm volatile("cp.async.wait_group 0;" ::: "memory");
        }
        __syncthreads();

        const uint32_t* sAh = smem + b * STGW + 0 * MATW;
        const uint32_t* sBh = smem + b * STGW + 1 * MATW;

#pragma unroll
        for (int kc = 0; kc < 16; kc += 8) {
            uint32_t ah[2][4];
            ldmx4(ah[0], sAh + (ar     ) * SLD + kc + ac4);
            ldmx4(ah[1], sAh + (ar + 16) * SLD + kc + ac4);
#pragma unroll
            for (int h = 0; h < 2; h++) {
                uint32_t bh0[4], bh1[4];
                ldmx4(bh0, sBh + (br + (2 * h)     * 16) * SLD + kc + bc4);
                ldmx4(bh1, sBh + (br + (2 * h + 1) * 16) * SLD + kc + bc4);
                const int p0 = 4 * h, p1 = 4 * h + 2;
                mma_f16(acc[0][p0],     ah[0], bh0[0], bh0[1]);
                mma_f16(acc[0][p0 + 1], ah[0], bh0[2], bh0[3]);
                mma_f16(acc[1][p0],     ah[1], bh0[0], bh0[1]);
                mma_f16(acc[1][p0 + 1], ah[1], bh0[2], bh0[3]);
                mma_f16(acc[0][p1],     ah[0], bh1[0], bh1[1]);
                mma_f16(acc[0][p1 + 1], ah[0], bh1[2], bh1[3]);
                mma_f16(acc[1][p1],     ah[1], bh1[0], bh1[1]);
                mma_f16(acc[1][p1 + 1], ah[1], bh1[2], bh1[3]);
            }
        }
        __syncthreads();
        if (++b >= NSTAGE) b = 0;
    }

    // ---- epilogue: frag (mf,nf) -> rows (g, g+8), cols nf*8 + tq*2 (+1) ----
#pragma unroll
    for (int mf = 0; mf < 2; mf++) {
#pragma unroll
        for (int nf = 0; nf < 8; nf++) {
            const int r0 = bm + m0 + mf * 16 + g;
            const int r1 = r0 + 8;
            const int cc = bn + n0 + nf * 8 + tq * 2;
            float v0 = acc[mf][nf][0], v1 = acc[mf][nf][1];
            float v2 = acc[mf][nf][2], v3 = acc[mf][nf][3];

            if (EPI == 1 || EPI == 3) {
                const float2 a0 = *(const float2*)(aux1 + (size_t)r0 * N + cc);
                const float2 a1 = *(const float2*)(aux1 + (size_t)r1 * N + cc);
                v0 += a0.x; v1 += a0.y; v2 += a1.x; v3 += a1.y;
            }
            if (EPI == 2 || EPI == 3) {
                const float2 bb = *(const float2*)(aux2 + cc);
                v0 += bb.x; v1 += bb.y; v2 += bb.x; v3 += bb.y;
            }
            if (EPI == 2) {
                v0 *= normcdff(v0); v1 *= normcdff(v1);
                v2 *= normcdff(v2); v3 *= normcdff(v3);
            }
            if (EPI == 2 || EPI == 4) {
                const int Nd2 = N >> 1;
                Chi[(size_t)r0 * Nd2 + (cc >> 1)] = hi2h(v0, v1);
                Chi[(size_t)r1 * Nd2 + (cc >> 1)] = hi2h(v2, v3);
            } else {
                *(float2*)(C + (size_t)r0 * N + cc) = make_float2(v0, v1);
                *(float2*)(C + (size_t)r1 * N + cc) = make_float2(v2, v3);
            }
        }
    }
}

// ---------------- attention: scores (H-split partials, packed fp16 qkv) ----------------
#define CH 64

__global__ __launch_bounds__(256) void attn_scores(
    const uint32_t* __restrict__ qkv, float* __restrict__ psc)
{
    __shared__ float Ks[63][CH + 1];
    __shared__ float Qs[32][CH + 1];

    const int tid = threadIdx.x;
    const int q0  = blockIdx.x * 32;
    const int b   = blockIdx.y;
    const int hs  = blockIdx.z;
    const int ti  = tid >> 3;
    const int wg  = tid & 7;

    float acc[4] = {0.f, 0.f, 0.f, 0.f};

    for (int h0 = hs * 256; h0 < hs * 256 + 256; h0 += CH) {
        for (int idx = tid; idx < 63 * 16; idx += 256) {
            int r  = idx >> 4;
            int c  = (idx & 15) << 2;
            int jb = q0 - 31 + r;
            uint2 u = make_uint2(0u, 0u);
            if (jb >= 0)
                u = *(const uint2*)(qkv + (size_t)(b * Sn + jb) * QKV_LD + KOFF + ((h0 + c) >> 1));
            float2 f0 = h2f2(u.x), f1 = h2f2(u.y);
            Ks[r][c] = f0.x; Ks[r][c + 1] = f0.y; Ks[r][c + 2] = f1.x; Ks[r][c + 3] = f1.y;
        }
        for (int idx = tid; idx < 32 * 16; idx += 256) {
            int r = idx >> 4;
            int c = (idx & 15) << 2;
            uint2 u = *(const uint2*)(qkv + (size_t)(b * Sn + q0 + r) * QKV_LD + ((h0 + c) >> 1));
            float2 f0 = h2f2(u.x), f1 = h2f2(u.y);
            Qs[r][c] = f0.x; Qs[r][c + 1] = f0.y; Qs[r][c + 2] = f1.x; Qs[r][c + 3] = f1.y;
        }
        __syncthreads();
#pragma unroll 8
        for (int kk = 0; kk < CH; kk++) {
            float qv = Qs[ti][kk];
#pragma unroll
            for (int j = 0; j < 4; j++)
                acc[j] += qv * Ks[ti + wg * 4 + j][kk];
        }
        __syncthreads();
    }
    const size_t base = ((size_t)hs * Mn + b * Sn + q0 + ti) * 32 + wg * 4;
#pragma unroll
    for (int j = 0; j < 4; j++) psc[base + j] = acc[j];
}

// ---------------- attention: softmax ----------------
__global__ __launch_bounds__(256) void attn_softmax(
    const float* __restrict__ psc, float* __restrict__ prob)
{
    const int warp = threadIdx.x >> 5, lane = threadIdx.x & 31;
    const int row  = blockIdx.x * 8 + warp;
    const int iq   = row & (Sn - 1);
    int wmin = 31 - iq; if (wmin < 0) wmin = 0;

    float s = 0.f;
#pragma unroll
    for (int hs = 0; hs < 4; hs++)
        s += psc[((size_t)hs * Mn + row) * 32 + lane];
    s *= (1.0f / 32.0f);

    const bool valid = (lane >= wmin);
    float m = valid ? s : -1e30f;
#pragma unroll
    for (int o = 16; o; o >>= 1) m = fmaxf(m, __shfl_xor_sync(0xffffffffu, m, o));
    float p = valid ? expf(s - m) : 0.f;
    float sum = p;
#pragma unroll
    for (int o = 16; o; o >>= 1) sum += __shfl_xor_sync(0xffffffffu, sum, o);
    prob[(size_t)row * 32 + lane] = p / sum;
}

// ---------------- attention: PV (packed fp16 qkv), emits fp16 pairs ----------------
__global__ __launch_bounds__(256) void attn_pv(
    const uint32_t* __restrict__ qkv, const float* __restrict__ prob,
    uint32_t* __restrict__ Ohi)
{
    __shared__ float Vs[63][132];

    const int tid = threadIdx.x;
    const int q0  = blockIdx.x * 32;
    const int b   = blockIdx.y;
    const int h0  = blockIdx.z * 128;
    const int ti  = tid >> 3;
    const int hg  = tid & 7;

    for (int idx = tid; idx < 63 * 32; idx += 256) {
        int r  = idx >> 5;
        int c  = (idx & 31) << 2;
        int jb = q0 - 31 + r;
        uint2 u = make_uint2(0u, 0u);
        if (jb >= 0)
            u = *(const uint2*)(qkv + (size_t)(b * Sn + jb) * QKV_LD + VOFF + ((h0 + c) >> 1));
        float2 f0 = h2f2(u.x), f1 = h2f2(u.y);
        Vs[r][c] = f0.x; Vs[r][c + 1] = f0.y; Vs[r][c + 2] = f1.x; Vs[r][c + 3] = f1.y;
    }
    float p[32];
    const float* pr = prob + (size_t)(b * Sn + q0 + ti) * 32;
#pragma unroll
    for (int w = 0; w < 32; w++) p[w] = pr[w];
    __syncthreads();

    float o[16];
#pragma unroll
    for (int c = 0; c < 16; c++) o[c] = 0.f;
#pragma unroll
    for (int w = 0; w < 32; w++) {
        const float pv = p[w];
        const float* vr = &Vs[ti + w][hg * 16];
#pragma unroll
        for (int c = 0; c < 16; c++) o[c] += pv * vr[c];
    }
    const size_t rowbase = (size_t)(b * Sn + q0 + ti) * (Hn / 2) + (h0 >> 1) + hg * 8;
#pragma unroll
    for (int c = 0; c < 16; c += 2)
        Ohi[rowbase + (c >> 1)] = hi2h(o[c], o[c + 1]);
}

// ---------------- layernorm: single-pass, fp32 in, fp16-pair out ----------------
__global__ __launch_bounds__(256) void ln_kernel(
    const float* __restrict__ X, const float* __restrict__ w,
    const float* __restrict__ bb, uint32_t* __restrict__ Yhi)
{
    const int row = blockIdx.x;
    const int tid = threadIdx.x;
    const float4 v = *(const float4*)(X + (size_t)row * Hn + tid * 4);

    float s  = v.x + v.y + v.z + v.w;
    float ss = v.x * v.x + v.y * v.y + v.z * v.z + v.w * v.w;

    __shared__ float red[64];
#pragma unroll
    for (int o = 16; o; o >>= 1) {
        s  += __shfl_down_sync(0xffffffffu, s,  o);
        ss += __shfl_down_sync(0xffffffffu, ss, o);
    }
    const int warp = tid >> 5, lane = tid & 31;
    if (lane == 0) { red[warp] = s; red[32 + warp] = ss; }
    __syncthreads();
    if (tid == 0) {
        float S = 0.f, SS = 0.f;
        for (int i = 0; i < 8; i++) { S += red[i]; SS += red[32 + i]; }
        red[0] = S; red[1] = SS;
    }
    __syncthreads();
    const float mu   = red[0] * (1.0f / Hn);
    const float var  = red[1] * (1.0f / Hn) - mu * mu;
    const float rstd = rsqrtf(var + 1e-5f);

    const float4 wv = *(const float4*)(w  + tid * 4);
    const float4 bv = *(const float4*)(bb + tid * 4);
    float y0 = (v.x - mu) * rstd * wv.x + bv.x;
    float y1 = (v.y - mu) * rstd * wv.y + bv.y;
    float y2 = (v.z - mu) * rstd * wv.z + bv.z;
    float y3 = (v.w - mu) * rstd * wv.w + bv.w;
    *(uint2*)(Yhi + (size_t)row * (Hn / 2) + tid * 2) = make_uint2(hi2h(y0, y1), hi2h(y2, y3));
}

// ---------------- launch ----------------
extern "C" void kernel_launch(void* const* d_in, const int* in_sizes, int n_in,
                              void* d_out, int out_size)
{
    const float* x   = (const float*)d_in[0];
    const float* Wq  = (const float*)d_in[1];
    const float* Wk  = (const float*)d_in[2];
    const float* Wv  = (const float*)d_in[3];
    const float* Wo  = (const float*)d_in[4];
    const float* lnw = (const float*)d_in[5];
    const float* lnb = (const float*)d_in[6];
    const float* W1  = (const float*)d_in[7];
    const float* b1  = (const float*)d_in[8];
    const float* W2  = (const float*)d_in[9];
    const float* b2  = (const float*)d_in[10];
    float* out = (float*)d_out;

    uint32_t *xh, *wqkvh, *woh, *w1h, *w2h, *qkvh, *ath, *lnh, *h1h;
    float *drft, *psc, *prob;
    cudaGetSymbolAddress((void**)&xh,    g_x_h);
    cudaGetSymbolAddress((void**)&wqkvh, g_wqkv_h);
    cudaGetSymbolAddress((void**)&woh,   g_wo_h);
    cudaGetSymbolAddress((void**)&w1h,   g_w1_h);
    cudaGetSymbolAddress((void**)&w2h,   g_w2_h);
    cudaGetSymbolAddress((void**)&qkvh,  g_qkv_h);
    cudaGetSymbolAddress((void**)&ath,   g_at_h);
    cudaGetSymbolAddress((void**)&lnh,   g_ln_h);
    cudaGetSymbolAddress((void**)&h1h,   g_h1_h);
    cudaGetSymbolAddress((void**)&drft,  g_drft);
    cudaGetSymbolAddress((void**)&psc,   g_psc);
    cudaGetSymbolAddress((void**)&prob,  g_prob);

    cudaFuncSetAttribute(gemm_mma<1>, cudaFuncAttributeMaxDynamicSharedMemorySize, GEMM_SMEM);
    cudaFuncSetAttribute(gemm_mma<2>, cudaFuncAttributeMaxDynamicSharedMemorySize, GEMM_SMEM);
    cudaFuncSetAttribute(gemm_mma<3>, cudaFuncAttributeMaxDynamicSharedMemorySize, GEMM_SMEM);
    cudaFuncSetAttribute(gemm_mma<4>, cudaFuncAttributeMaxDynamicSharedMemorySize, GEMM_SMEM);

    // fused conversion (one launch): x + all weights -> fp16 pairs
    const int nX = Mn * Hn / 4;         // 2097152
    const int nW = Hn * Hn / 4;         // 262144
    const int nH = Hn * Hn / 8;         // 131072
    const int total = nX + 4 * nW + 2 * nH;
    conv_all<<<(total + 255) / 256, 256>>>(
        x,  xh,            nX,
        Wq, wqkvh,             nW,
        Wk, wqkvh + 1 * nW * 2, nW,     // each segment is nW float4 = 2*nW u32... offsets in u32
        Wv, wqkvh + 2 * nW * 2, nW,
        Wo, woh, nW,
        W1, w1h, nH,
        W2, w2h, nH);

    dim3 gridQKV(3 * Hn / BN,   Mn / BM);   // (24, 64)
    dim3 gridH  (Hn / BN,       Mn / BM);   // (8, 64)
    dim3 gridH2 ((Hn / 2) / BN, Mn / BM);   // (4, 64)

    // fused QKV projection -> packed fp16 [q|k|v] rows
    gemm_mma<4><<<gridQKV, 256, GEMM_SMEM>>>(xh, wqkvh, nullptr, qkvh, Mn, 3 * Hn, Hn, nullptr, nullptr);

    // banded attention (packed fp16 qkv)
    attn_scores <<<dim3(Sn / 32, Bn, 4), 256>>>(qkvh, psc);
    attn_softmax<<<Mn / 8, 256>>>(psc, prob);
    attn_pv     <<<dim3(Sn / 32, Bn, 8), 256>>>(qkvh, prob, ath);

    // draft = x + attn @ Wo^T  (fp32 out)
    gemm_mma<1><<<gridH, 256, GEMM_SMEM>>>(ath, woh, drft, nullptr, Mn, Hn, Hn, x, nullptr);

    // layernorm -> fp16 pairs (single pass)
    ln_kernel<<<Mn, 256>>>(drft, lnw, lnb, lnh);

    // h1 = gelu(ln @ W1^T + b1) -> fp16 pairs
    gemm_mma<2><<<gridH2, 256, GEMM_SMEM>>>(lnh, w1h, nullptr, h1h, Mn, Hn / 2, Hn, nullptr, b1);

    // out = draft + h1 @ W2^T + b2  (fp32)
    gemm_mma<3><<<gridH, 256, GEMM_SMEM>>>(h1h, w2h, out, nullptr, Mn, Hn, Hn / 2, drft, b2);
}

// round 14
// speedup vs baseline: 1.0899x; 1.0039x over previous
#include <cuda_runtime.h>
#include <cuda_fp16.h>
#include <math.h>
#include <stdint.h>

#define Bn   2
#define Sn   4096
#define Hn   1024
#define Mn   (Bn * Sn)       // 8192 rows
#define WIN  32

// ---------------- scratch (no allocations allowed) ----------------
// fp16 pair buffers (u32 = two fp16, even k in low half)
__device__ uint32_t g_x_h   [Mn * Hn / 2];
__device__ uint32_t g_wqkv_h[3 * Hn * Hn / 2];   // rows: [Wq(1024) | Wk(1024) | Wv(1024)]
__device__ uint32_t g_wo_h  [Hn * Hn / 2];
__device__ uint32_t g_w1_h  [(Hn / 2) * Hn / 2];
__device__ uint32_t g_w2_h  [Hn * (Hn / 2) / 2];
__device__ uint32_t g_qkv_h [Mn * 3 * Hn / 2];   // per row: [q(512u32) | k(512) | v(512)]
__device__ uint32_t g_at_h  [Mn * Hn / 2];
__device__ uint32_t g_dr_h  [Mn * Hn / 2];       // draft, fp16 pairs
__device__ uint32_t g_ln_h  [Mn * Hn / 2];
__device__ uint32_t g_h1_h  [Mn * Hn / 4];
__device__ float g_psc [4 * Mn * 32];
__device__ float g_prob[Mn * 32];

#define QKV_LD (3 * Hn / 2)   // 1536 u32 per row
#define KOFF   (Hn / 2)       // 512
#define VOFF   (Hn)           // 1024

// ---------------- fp16 helpers ----------------
__device__ __forceinline__ uint32_t pack2_h(__half a, __half b) {
    __half2 t; t.x = a; t.y = b;
    return *(uint32_t*)&t;
}
__device__ __forceinline__ uint32_t hi2h(float x, float y) {
    return pack2_h(__float2half_rn(x), __float2half_rn(y));
}
__device__ __forceinline__ float2 h2f2(uint32_t u) {
    __half2 h = *(__half2*)&u;
    return __half22float2(h);
}
__device__ __forceinline__ void mma_f16(float c[4], const uint32_t a[4], uint32_t b0, uint32_t b1) {
    asm("mma.sync.aligned.m16n8k16.row.col.f32.f16.f16.f32 "
        "{%0,%1,%2,%3}, {%4,%5,%6,%7}, {%8,%9}, {%0,%1,%2,%3};\n"
        : "+f"(c[0]), "+f"(c[1]), "+f"(c[2]), "+f"(c[3])
        : "r"(a[0]), "r"(a[1]), "r"(a[2]), "r"(a[3]), "r"(b0), "r"(b1));
}
__device__ __forceinline__ void ldmx4(uint32_t r[4], const uint32_t* p) {
    uint32_t a = (uint32_t)__cvta_generic_to_shared(p);
    asm volatile("ldmatrix.sync.aligned.m8n8.x4.shared.b16 {%0,%1,%2,%3}, [%4];"
        : "=r"(r[0]), "=r"(r[1]), "=r"(r[2]), "=r"(r[3]) : "r"(a));
}
__device__ __forceinline__ void cp16(uint32_t sdst, const void* gsrc) {
    asm volatile("cp.async.cg.shared.global [%0], [%1], 16;" :: "r"(sdst), "l"(gsrc));
}
#define CP_COMMIT() asm volatile("cp.async.commit_group;" ::: "memory")

// ---------------- fused conversion: all tensors -> fp16 pairs in one launch ----------------
__global__ __launch_bounds__(256) void conv_all(
    const float* s0, uint32_t* d0, int n0,   // x
    const float* s1, uint32_t* d1, int n1,   // Wq
    const float* s2, uint32_t* d2, int n2,   // Wk
    const float* s3, uint32_t* d3, int n3,   // Wv
    const float* s4, uint32_t* d4, int n4c,  // Wo
    const float* s5, uint32_t* d5, int n5,   // W1
    const float* s6, uint32_t* d6, int n6)   // W2
{
    int i = blockIdx.x * 256 + threadIdx.x;
    const float* s; uint32_t* d;
    if      (i < n0)                        { s = s0; d = d0; }
    else if ((i -= n0) < n1)                { s = s1; d = d1; }
    else if ((i -= n1) < n2)                { s = s2; d = d2; }
    else if ((i -= n2) < n3)                { s = s3; d = d3; }
    else if ((i -= n3) < n4c)               { s = s4; d = d4; }
    else if ((i -= n4c) < n5)               { s = s5; d = d5; }
    else if ((i -= n5) < n6)                { s = s6; d = d6; }
    else return;
    float4 v = ((const float4*)s)[i];
    ((uint2*)d)[i] = make_uint2(hi2h(v.x, v.y), hi2h(v.z, v.w));
}

// ---------------- GEMM: C[M,N] = A[M,K] @ B[N,K]^T, fp16, 3-stage cp.async ----------------
// EPI 2: fp16 out = gelu(acc + aux2[n])          (W1)
// EPI 4: fp16 out plain                          (QKV)
// EPI 5: fp16 out = aux1(fp32) + acc             (Wo: draft)
// EPI 6: fp32 out = h2f(aux1h) + acc + aux2[n]   (W2: final)
#define BM 128
#define BN 128
#define SLD 20                         // u32 row stride (16 used + 4 pad)
#define MATW (BM * SLD)                // u32 per matrix tile (2560)
#define STGW (2 * MATW)                // u32 per stage (Ah, Bh)
#define NSTAGE 3
#define GEMM_SMEM (NSTAGE * STGW * 4)  // bytes (61440)

template<int EPI>
__global__ __launch_bounds__(256, 2) void gemm_mma(
    const uint32_t* __restrict__ Ahg, const uint32_t* __restrict__ Bhg,
    float* __restrict__ C, uint32_t* __restrict__ Chi,
    int M, int N, int K,
    const float* __restrict__ aux1, const float* __restrict__ aux2,
    const uint32_t* __restrict__ aux1h)
{
    extern __shared__ uint32_t smem[];

    const int Kd2  = K >> 1;
    const int nt   = Kd2 >> 4;          // k-tiles of 16 u32 (32 elements)
    const int tid  = threadIdx.x;
    const int wid  = tid >> 5;
    const int lane = tid & 31;
    const int g    = lane >> 2;
    const int tq   = lane & 3;

    const int bm = blockIdx.y * BM;
    const int bn = blockIdx.x * BN;
    const int m0 = (wid & 3) * 32;
    const int n0 = (wid >> 2) * 64;

    const int sr0 = tid >> 2,         sc0 = (tid & 3) << 2;
    const int sr1 = (tid + 256) >> 2, sc1 = ((tid + 256) & 3) << 2;
    const uint32_t smem_base = (uint32_t)__cvta_generic_to_shared(smem);

    float acc[2][8][4];
#pragma unroll
    for (int i = 0; i < 2; i++)
#pragma unroll
        for (int j = 0; j < 8; j++)
#pragma unroll
            for (int r = 0; r < 4; r++) acc[i][j][r] = 0.f;

    const int ar  = m0 + ((lane & 15) >> 3) * 8 + (lane & 7);
    const int ac4 = (lane >> 4) * 4;
    const int br  = n0 + (lane >> 4) * 8 + (lane & 7);
    const int bc4 = ((lane & 15) >> 3) * 4;

    auto stage = [&](int k, int b) {
        const uint32_t sbase = smem_base + (uint32_t)(b * STGW) * 4u;
        const int koff = k * 16;
        {
            const size_t ga = (size_t)(bm + sr0) * Kd2 + koff + sc0;
            const size_t gb = (size_t)(bn + sr0) * Kd2 + koff + sc0;
            const uint32_t so = (uint32_t)(sr0 * SLD + sc0) * 4u;
            cp16(sbase + 0 * MATW * 4 + so, Ahg + ga);
            cp16(sbase + 1 * MATW * 4 + so, Bhg + gb);
        }
        {
            const size_t ga = (size_t)(bm + sr1) * Kd2 + koff + sc1;
            const size_t gb = (size_t)(bn + sr1) * Kd2 + koff + sc1;
            const uint32_t so = (uint32_t)(sr1 * SLD + sc1) * 4u;
            cp16(sbase + 0 * MATW * 4 + so, Ahg + ga);
            cp16(sbase + 1 * MATW * 4 + so, Bhg + gb);
        }
    };

    stage(0, 0);
    CP_COMMIT();
    if (nt > 1) { stage(1, 1); CP_COMMIT(); }

    int b = 0;
    for (int k = 0; k < nt; k++) {
        if (k + 2 < nt) {
            int bs = b + 2; if (bs >= NSTAGE) bs -= NSTAGE;
            stage(k + 2, bs);
            CP_COMMIT();
            asm volatile("cp.async.wait_group 2;" ::: "memory");
        } else if (k + 1 < nt) {
            asm volatile("cp.async.wait_group 1;" ::: "memory");
        } else {
            asm volatile("cp.async.wait_group 0;" ::: "memory");
        }
        __syncthreads();

        const uint32_t* sAh = smem + b * STGW + 0 * MATW;
        const uint32_t* sBh = smem + b * STGW + 1 * MATW;

#pragma unroll
        for (int kc = 0; kc < 16; kc += 8) {
            uint32_t ah[2][4];
            ldmx4(ah[0], sAh + (ar     ) * SLD + kc + ac4);
            ldmx4(ah[1], sAh + (ar + 16) * SLD + kc + ac4);
#pragma unroll
            for (int h = 0; h < 2; h++) {
                uint32_t bh0[4], bh1[4];
                ldmx4(bh0, sBh + (br + (2 * h)     * 16) * SLD + kc + bc4);
                ldmx4(bh1, sBh + (br + (2 * h + 1) * 16) * SLD + kc + bc4);
                const int p0 = 4 * h, p1 = 4 * h + 2;
                mma_f16(acc[0][p0],     ah[0], bh0[0], bh0[1]);
                mma_f16(acc[0][p0 + 1], ah[0], bh0[2], bh0[3]);
                mma_f16(acc[1][p0],     ah[1], bh0[0], bh0[1]);
                mma_f16(acc[1][p0 + 1], ah[1], bh0[2], bh0[3]);
                mma_f16(acc[0][p1],     ah[0], bh1[0], bh1[1]);
                mma_f16(acc[0][p1 + 1], ah[0], bh1[2], bh1[3]);
                mma_f16(acc[1][p1],     ah[1], bh1[0], bh1[1]);
                mma_f16(acc[1][p1 + 1], ah[1], bh1[2], bh1[3]);
            }
        }
        __syncthreads();
        if (++b >= NSTAGE) b = 0;
    }

    // ---- epilogue: frag (mf,nf) -> rows (g, g+8), cols nf*8 + tq*2 (+1) ----
#pragma unroll
    for (int mf = 0; mf < 2; mf++) {
#pragma unroll
        for (int nf = 0; nf < 8; nf++) {
            const int r0 = bm + m0 + mf * 16 + g;
            const int r1 = r0 + 8;
            const int cc = bn + n0 + nf * 8 + tq * 2;
            const int Nd2 = N >> 1;
            float v0 = acc[mf][nf][0], v1 = acc[mf][nf][1];
            float v2 = acc[mf][nf][2], v3 = acc[mf][nf][3];

            if (EPI == 5) {   // fp32 residual add
                const float2 a0 = *(const float2*)(aux1 + (size_t)r0 * N + cc);
                const float2 a1 = *(const float2*)(aux1 + (size_t)r1 * N + cc);
                v0 += a0.x; v1 += a0.y; v2 += a1.x; v3 += a1.y;
            }
            if (EPI == 6) {   // fp16-pair residual add
                const float2 a0 = h2f2(aux1h[(size_t)r0 * Nd2 + (cc >> 1)]);
                const float2 a1 = h2f2(aux1h[(size_t)r1 * Nd2 + (cc >> 1)]);
                v0 += a0.x; v1 += a0.y; v2 += a1.x; v3 += a1.y;
            }
            if (EPI == 2 || EPI == 6) {
                const float2 bb = *(const float2*)(aux2 + cc);
                v0 += bb.x; v1 += bb.y; v2 += bb.x; v3 += bb.y;
            }
            if (EPI == 2) {
                v0 *= normcdff(v0); v1 *= normcdff(v1);
                v2 *= normcdff(v2); v3 *= normcdff(v3);
            }
            if (EPI == 2 || EPI == 4 || EPI == 5) {
                Chi[(size_t)r0 * Nd2 + (cc >> 1)] = hi2h(v0, v1);
                Chi[(size_t)r1 * Nd2 + (cc >> 1)] = hi2h(v2, v3);
            } else {
                *(float2*)(C + (size_t)r0 * N + cc) = make_float2(v0, v1);
                *(float2*)(C + (size_t)r1 * N + cc) = make_float2(v2, v3);
            }
        }
    }
}

// ---------------- attention: scores (H-split partials, packed fp16 qkv) ----------------
#define CH 64

__global__ __launch_bounds__(256) void attn_scores(
    const uint32_t* __restrict__ qkv, float* __restrict__ psc)
{
    __shared__ float Ks[63][CH + 1];
    __shared__ float Qs[32][CH + 1];

    const int tid = threadIdx.x;
    const int q0  = blockIdx.x * 32;
    const int b   = blockIdx.y;
    const int hs  = blockIdx.z;
    const int ti  = tid >> 3;
    const int wg  = tid & 7;

    float acc[4] = {0.f, 0.f, 0.f, 0.f};

    for (int h0 = hs * 256; h0 < hs * 256 + 256; h0 += CH) {
        for (int idx = tid; idx < 63 * 16; idx += 256) {
            int r  = idx >> 4;
            int c  = (idx & 15) << 2;
            int jb = q0 - 31 + r;
            uint2 u = make_uint2(0u, 0u);
            if (jb >= 0)
                u = *(const uint2*)(qkv + (size_t)(b * Sn + jb) * QKV_LD + KOFF + ((h0 + c) >> 1));
            float2 f0 = h2f2(u.x), f1 = h2f2(u.y);
            Ks[r][c] = f0.x; Ks[r][c + 1] = f0.y; Ks[r][c + 2] = f1.x; Ks[r][c + 3] = f1.y;
        }
        for (int idx = tid; idx < 32 * 16; idx += 256) {
            int r = idx >> 4;
            int c = (idx & 15) << 2;
            uint2 u = *(const uint2*)(qkv + (size_t)(b * Sn + q0 + r) * QKV_LD + ((h0 + c) >> 1));
            float2 f0 = h2f2(u.x), f1 = h2f2(u.y);
            Qs[r][c] = f0.x; Qs[r][c + 1] = f0.y; Qs[r][c + 2] = f1.x; Qs[r][c + 3] = f1.y;
        }
        __syncthreads();
#pragma unroll 8
        for (int kk = 0; kk < CH; kk++) {
            float qv = Qs[ti][kk];
#pragma unroll
            for (int j = 0; j < 4; j++)
                acc[j] += qv * Ks[ti + wg * 4 + j][kk];
        }
        __syncthreads();
    }
    const size_t base = ((size_t)hs * Mn + b * Sn + q0 + ti) * 32 + wg * 4;
#pragma unroll
    for (int j = 0; j < 4; j++) psc[base + j] = acc[j];
}

// ---------------- attention: softmax ----------------
__global__ __launch_bounds__(256) void attn_softmax(
    const float* __restrict__ psc, float* __restrict__ prob)
{
    const int warp = threadIdx.x >> 5, lane = threadIdx.x & 31;
    const int row  = blockIdx.x * 8 + warp;
    const int iq   = row & (Sn - 1);
    int wmin = 31 - iq; if (wmin < 0) wmin = 0;

    float s = 0.f;
#pragma unroll
    for (int hs = 0; hs < 4; hs++)
        s += psc[((size_t)hs * Mn + row) * 32 + lane];
    s *= (1.0f / 32.0f);

    const bool valid = (lane >= wmin);
    float m = valid ? s : -1e30f;
#pragma unroll
    for (int o = 16; o; o >>= 1) m = fmaxf(m, __shfl_xor_sync(0xffffffffu, m, o));
    float p = valid ? expf(s - m) : 0.f;
    float sum = p;
#pragma unroll
    for (int o = 16; o; o >>= 1) sum += __shfl_xor_sync(0xffffffffu, sum, o);
    prob[(size_t)row * 32 + lane] = p / sum;
}

// ---------------- attention: PV (packed fp16 qkv), emits fp16 pairs ----------------
__global__ __launch_bounds__(256) void attn_pv(
    const uint32_t* __restrict__ qkv, const float* __restrict__ prob,
    uint32_t* __restrict__ Ohi)
{
    __shared__ float Vs[63][132];

    const int tid = threadIdx.x;
    const int q0  = blockIdx.x * 32;
    const int b   = blockIdx.y;
    const int h0  = blockIdx.z * 128;
    const int ti  = tid >> 3;
    const int hg  = tid & 7;

    for (int idx = tid; idx < 63 * 32; idx += 256) {
        int r  = idx >> 5;
        int c  = (idx & 31) << 2;
        int jb = q0 - 31 + r;
        uint2 u = make_uint2(0u, 0u);
        if (jb >= 0)
            u = *(const uint2*)(qkv + (size_t)(b * Sn + jb) * QKV_LD + VOFF + ((h0 + c) >> 1));
        float2 f0 = h2f2(u.x), f1 = h2f2(u.y);
        Vs[r][c] = f0.x; Vs[r][c + 1] = f0.y; Vs[r][c + 2] = f1.x; Vs[r][c + 3] = f1.y;
    }
    float p[32];
    const float* pr = prob + (size_t)(b * Sn + q0 + ti) * 32;
#pragma unroll
    for (int w = 0; w < 32; w++) p[w] = pr[w];
    __syncthreads();

    float o[16];
#pragma unroll
    for (int c = 0; c < 16; c++) o[c] = 0.f;
#pragma unroll
    for (int w = 0; w < 32; w++) {
        const float pv = p[w];
        const float* vr = &Vs[ti + w][hg * 16];
#pragma unroll
        for (int c = 0; c < 16; c++) o[c] += pv * vr[c];
    }
    const size_t rowbase = (size_t)(b * Sn + q0 + ti) * (Hn / 2) + (h0 >> 1) + hg * 8;
#pragma unroll
    for (int c = 0; c < 16; c += 2)
        Ohi[rowbase + (c >> 1)] = hi2h(o[c], o[c + 1]);
}

// ---------------- layernorm: single-pass, fp16-pair in, fp16-pair out ----------------
// 256 threads x 2 u32 (4 halves) = 1024 = Hn
__global__ __launch_bounds__(256) void ln_kernel(
    const uint32_t* __restrict__ Xh, const float* __restrict__ w,
    const float* __restrict__ bb, uint32_t* __restrict__ Yhi)
{
    const int row = blockIdx.x;
    const int tid = threadIdx.x;
    const uint2 u = *(const uint2*)(Xh + (size_t)row * (Hn / 2) + tid * 2);
    const float2 f0 = h2f2(u.x), f1 = h2f2(u.y);

    float s  = f0.x + f0.y + f1.x + f1.y;
    float ss = f0.x * f0.x + f0.y * f0.y + f1.x * f1.x + f1.y * f1.y;

    __shared__ float red[64];
#pragma unroll
    for (int o = 16; o; o >>= 1) {
        s  += __shfl_down_sync(0xffffffffu, s,  o);
        ss += __shfl_down_sync(0xffffffffu, ss, o);
    }
    const int warp = tid >> 5, lane = tid & 31;
    if (lane == 0) { red[warp] = s; red[32 + warp] = ss; }
    __syncthreads();
    if (tid == 0) {
        float S = 0.f, SS = 0.f;
        for (int i = 0; i < 8; i++) { S += red[i]; SS += red[32 + i]; }
        red[0] = S; red[1] = SS;
    }
    __syncthreads();
    const float mu   = red[0] * (1.0f / Hn);
    const float var  = red[1] * (1.0f / Hn) - mu * mu;
    const float rstd = rsqrtf(var + 1e-5f);

    const float4 wv = *(const float4*)(w  + tid * 4);
    const float4 bv = *(const float4*)(bb + tid * 4);
    float y0 = (f0.x - mu) * rstd * wv.x + bv.x;
    float y1 = (f0.y - mu) * rstd * wv.y + bv.y;
    float y2 = (f1.x - mu) * rstd * wv.z + bv.z;
    float y3 = (f1.y - mu) * rstd * wv.w + bv.w;
    *(uint2*)(Yhi + (size_t)row * (Hn / 2) + tid * 2) = make_uint2(hi2h(y0, y1), hi2h(y2, y3));
}

// ---------------- launch ----------------
extern "C" void kernel_launch(void* const* d_in, const int* in_sizes, int n_in,
                              void* d_out, int out_size)
{
    const float* x   = (const float*)d_in[0];
    const float* Wq  = (const float*)d_in[1];
    const float* Wk  = (const float*)d_in[2];
    const float* Wv  = (const float*)d_in[3];
    const float* Wo  = (const float*)d_in[4];
    const float* lnw = (const float*)d_in[5];
    const float* lnb = (const float*)d_in[6];
    const float* W1  = (const float*)d_in[7];
    const float* b1  = (const float*)d_in[8];
    const float* W2  = (const float*)d_in[9];
    const float* b2  = (const float*)d_in[10];
    float* out = (float*)d_out;

    uint32_t *xh, *wqkvh, *woh, *w1h, *w2h, *qkvh, *ath, *drh, *lnh, *h1h;
    float *psc, *prob;
    cudaGetSymbolAddress((void**)&xh,    g_x_h);
    cudaGetSymbolAddress((void**)&wqkvh, g_wqkv_h);
    cudaGetSymbolAddress((void**)&woh,   g_wo_h);
    cudaGetSymbolAddress((void**)&w1h,   g_w1_h);
    cudaGetSymbolAddress((void**)&w2h,   g_w2_h);
    cudaGetSymbolAddress((void**)&qkvh,  g_qkv_h);
    cudaGetSymbolAddress((void**)&ath,   g_at_h);
    cudaGetSymbolAddress((void**)&drh,   g_dr_h);
    cudaGetSymbolAddress((void**)&lnh,   g_ln_h);
    cudaGetSymbolAddress((void**)&h1h,   g_h1_h);
    cudaGetSymbolAddress((void**)&psc,   g_psc);
    cudaGetSymbolAddress((void**)&prob,  g_prob);

    cudaFuncSetAttribute(gemm_mma<2>, cudaFuncAttributeMaxDynamicSharedMemorySize, GEMM_SMEM);
    cudaFuncSetAttribute(gemm_mma<4>, cudaFuncAttributeMaxDynamicSharedMemorySize, GEMM_SMEM);
    cudaFuncSetAttribute(gemm_mma<5>, cudaFuncAttributeMaxDynamicSharedMemorySize, GEMM_SMEM);
    cudaFuncSetAttribute(gemm_mma<6>, cudaFuncAttributeMaxDynamicSharedMemorySize, GEMM_SMEM);

    // fused conversion (one launch): x + all weights -> fp16 pairs
    const int nX = Mn * Hn / 4;
    const int nW = Hn * Hn / 4;
    const int nH = Hn * Hn / 8;
    const int total = nX + 4 * nW + 2 * nH;
    conv_all<<<(total + 255) / 256, 256>>>(
        x,  xh, nX,
        Wq, wqkvh,              nW,
        Wk, wqkvh + 1 * nW * 2, nW,
        Wv, wqkvh + 2 * nW * 2, nW,
        Wo, woh, nW,
        W1, w1h, nH,
        W2, w2h, nH);

    dim3 gridQKV(3 * Hn / BN,   Mn / BM);   // (24, 64)
    dim3 gridH  (Hn / BN,       Mn / BM);   // (8, 64)
    dim3 gridH2 ((Hn / 2) / BN, Mn / BM);   // (4, 64)

    // fused QKV projection -> packed fp16 [q|k|v] rows
    gemm_mma<4><<<gridQKV, 256, GEMM_SMEM>>>(xh, wqkvh, nullptr, qkvh, Mn, 3 * Hn, Hn, nullptr, nullptr, nullptr);

    // banded attention (packed fp16 qkv)
    attn_scores <<<dim3(Sn / 32, Bn, 4), 256>>>(qkvh, psc);
    attn_softmax<<<Mn / 8, 256>>>(psc, prob);
    attn_pv     <<<dim3(Sn / 32, Bn, 8), 256>>>(qkvh, prob, ath);

    // draft = fp16(x + attn @ Wo^T)
    gemm_mma<5><<<gridH, 256, GEMM_SMEM>>>(ath, woh, nullptr, drh, Mn, Hn, Hn, x, nullptr, nullptr);

    // layernorm (fp16 in/out, single pass)
    ln_kernel<<<Mn, 256>>>(drh, lnw, lnb, lnh);

    // h1 = gelu(ln @ W1^T + b1) -> fp16 pairs
    gemm_mma<2><<<gridH2, 256, GEMM_SMEM>>>(lnh, w1h, nullptr, h1h, Mn, Hn / 2, Hn, nullptr, b1, nullptr);

    // out = draft(fp16) + h1 @ W2^T + b2  (fp32)
    gemm_mma<6><<<gridH, 256, GEMM_SMEM>>>(h1h, w2h, out, nullptr, Mn, Hn, Hn / 2, nullptr, b2, drh);
}

// round 15
// speedup vs baseline: 1.2074x; 1.1078x over previous
#include <cuda_runtime.h>
#include <cuda_fp16.h>
#include <math.h>
#include <stdint.h>

#define Bn   2
#define Sn   4096
#define Hn   1024
#define Mn   (Bn * Sn)       // 8192 rows
#define WIN  32

// ---------------- scratch (no allocations allowed) ----------------
__device__ uint32_t g_x_h   [Mn * Hn / 2];
__device__ uint32_t g_wqkv_h[3 * Hn * Hn / 2];   // rows: [Wq | Wk | Wv]
__device__ uint32_t g_wo_h  [Hn * Hn / 2];
__device__ uint32_t g_w1_h  [(Hn / 2) * Hn / 2];
__device__ uint32_t g_w2_h  [Hn * (Hn / 2) / 2];
__device__ uint32_t g_qkv_h [Mn * 3 * Hn / 2];   // per row: [q(512u32) | k(512) | v(512)]
__device__ uint32_t g_at_h  [Mn * Hn / 2];
__device__ uint32_t g_dr_h  [Mn * Hn / 2];       // draft, fp16 pairs
__device__ uint32_t g_ln_h  [Mn * Hn / 2];
__device__ uint32_t g_h1_h  [Mn * Hn / 4];
__device__ float g_psc [4 * Mn * 32];
__device__ float g_prob[Mn * 32];

#define QKV_LD (3 * Hn / 2)   // 1536 u32 per row
#define KOFF   (Hn / 2)       // 512
#define VOFF   (Hn)           // 1024

// ---------------- fp16 helpers ----------------
__device__ __forceinline__ uint32_t pack2_h(__half a, __half b) {
    __half2 t; t.x = a; t.y = b;
    return *(uint32_t*)&t;
}
__device__ __forceinline__ uint32_t hi2h(float x, float y) {
    return pack2_h(__float2half_rn(x), __float2half_rn(y));
}
__device__ __forceinline__ float2 h2f2(uint32_t u) {
    __half2 h = *(__half2*)&u;
    return __half22float2(h);
}
__device__ __forceinline__ void mma_f16(float c[4], const uint32_t a[4], uint32_t b0, uint32_t b1) {
    asm("mma.sync.aligned.m16n8k16.row.col.f32.f16.f16.f32 "
        "{%0,%1,%2,%3}, {%4,%5,%6,%7}, {%8,%9}, {%0,%1,%2,%3};\n"
        : "+f"(c[0]), "+f"(c[1]), "+f"(c[2]), "+f"(c[3])
        : "r"(a[0]), "r"(a[1]), "r"(a[2]), "r"(a[3]), "r"(b0), "r"(b1));
}
__device__ __forceinline__ void ldmx4(uint32_t r[4], const uint32_t* p) {
    uint32_t a = (uint32_t)__cvta_generic_to_shared(p);
    asm volatile("ldmatrix.sync.aligned.m8n8.x4.shared.b16 {%0,%1,%2,%3}, [%4];"
        : "=r"(r[0]), "=r"(r[1]), "=r"(r[2]), "=r"(r[3]) : "r"(a));
}
__device__ __forceinline__ void cp16(uint32_t sdst, const void* gsrc) {
    asm volatile("cp.async.cg.shared.global [%0], [%1], 16;" :: "r"(sdst), "l"(gsrc));
}
#define CP_COMMIT() asm volatile("cp.async.commit_group;" ::: "memory")

// ---------------- fused conversion ----------------
__global__ __launch_bounds__(256) void conv_all(
    const float* s0, uint32_t* d0, int n0,
    const float* s1, uint32_t* d1, int n1,
    const float* s2, uint32_t* d2, int n2,
    const float* s3, uint32_t* d3, int n3,
    const float* s4, uint32_t* d4, int n4c,
    const float* s5, uint32_t* d5, int n5,
    const float* s6, uint32_t* d6, int n6)
{
    int i = blockIdx.x * 256 + threadIdx.x;
    const float* s; uint32_t* d;
    if      (i < n0)                        { s = s0; d = d0; }
    else if ((i -= n0) < n1)                { s = s1; d = d1; }
    else if ((i -= n1) < n2)                { s = s2; d = d2; }
    else if ((i -= n2) < n3)                { s = s3; d = d3; }
    else if ((i -= n3) < n4c)               { s = s4; d = d4; }
    else if ((i -= n4c) < n5)               { s = s5; d = d5; }
    else if ((i -= n5) < n6)                { s = s6; d = d6; }
    else return;
    float4 v = ((const float4*)s)[i];
    ((uint2*)d)[i] = make_uint2(hi2h(v.x, v.y), hi2h(v.z, v.w));
}

// ---------------- GEMM (unchanged from R14) ----------------
#define BM 128
#define BN 128
#define SLD 20
#define MATW (BM * SLD)
#define STGW (2 * MATW)
#define NSTAGE 3
#define GEMM_SMEM (NSTAGE * STGW * 4)

template<int EPI>
__global__ __launch_bounds__(256, 2) void gemm_mma(
    const uint32_t* __restrict__ Ahg, const uint32_t* __restrict__ Bhg,
    float* __restrict__ C, uint32_t* __restrict__ Chi,
    int M, int N, int K,
    const float* __restrict__ aux1, const float* __restrict__ aux2,
    const uint32_t* __restrict__ aux1h)
{
    extern __shared__ uint32_t smem[];

    const int Kd2  = K >> 1;
    const int nt   = Kd2 >> 4;
    const int tid  = threadIdx.x;
    const int wid  = tid >> 5;
    const int lane = tid & 31;
    const int g    = lane >> 2;
    const int tq   = lane & 3;

    const int bm = blockIdx.y * BM;
    const int bn = blockIdx.x * BN;
    const int m0 = (wid & 3) * 32;
    const int n0 = (wid >> 2) * 64;

    const int sr0 = tid >> 2,         sc0 = (tid & 3) << 2;
    const int sr1 = (tid + 256) >> 2, sc1 = ((tid + 256) & 3) << 2;
    const uint32_t smem_base = (uint32_t)__cvta_generic_to_shared(smem);

    float acc[2][8][4];
#pragma unroll
    for (int i = 0; i < 2; i++)
#pragma unroll
        for (int j = 0; j < 8; j++)
#pragma unroll
            for (int r = 0; r < 4; r++) acc[i][j][r] = 0.f;

    const int ar  = m0 + ((lane & 15) >> 3) * 8 + (lane & 7);
    const int ac4 = (lane >> 4) * 4;
    const int br  = n0 + (lane >> 4) * 8 + (lane & 7);
    const int bc4 = ((lane & 15) >> 3) * 4;

    auto stage = [&](int k, int b) {
        const uint32_t sbase = smem_base + (uint32_t)(b * STGW) * 4u;
        const int koff = k * 16;
        {
            const size_t ga = (size_t)(bm + sr0) * Kd2 + koff + sc0;
            const size_t gb = (size_t)(bn + sr0) * Kd2 + koff + sc0;
            const uint32_t so = (uint32_t)(sr0 * SLD + sc0) * 4u;
            cp16(sbase + 0 * MATW * 4 + so, Ahg + ga);
            cp16(sbase + 1 * MATW * 4 + so, Bhg + gb);
        }
        {
            const size_t ga = (size_t)(bm + sr1) * Kd2 + koff + sc1;
            const size_t gb = (size_t)(bn + sr1) * Kd2 + koff + sc1;
            const uint32_t so = (uint32_t)(sr1 * SLD + sc1) * 4u;
            cp16(sbase + 0 * MATW * 4 + so, Ahg + ga);
            cp16(sbase + 1 * MATW * 4 + so, Bhg + gb);
        }
    };

    stage(0, 0);
    CP_COMMIT();
    if (nt > 1) { stage(1, 1); CP_COMMIT(); }

    int b = 0;
    for (int k = 0; k < nt; k++) {
        if (k + 2 < nt) {
            int bs = b + 2; if (bs >= NSTAGE) bs -= NSTAGE;
            stage(k + 2, bs);
            CP_COMMIT();
            asm volatile("cp.async.wait_group 2;" ::: "memory");
        } else if (k + 1 < nt) {
            asm volatile("cp.async.wait_group 1;" ::: "memory");
        } else {
            asm volatile("cp.async.wait_group 0;" ::: "memory");
        }
        __syncthreads();

        const uint32_t* sAh = smem + b * STGW + 0 * MATW;
        const uint32_t* sBh = smem + b * STGW + 1 * MATW;

#pragma unroll
        for (int kc = 0; kc < 16; kc += 8) {
            uint32_t ah[2][4];
            ldmx4(ah[0], sAh + (ar     ) * SLD + kc + ac4);
            ldmx4(ah[1], sAh + (ar + 16) * SLD + kc + ac4);
#pragma unroll
            for (int h = 0; h < 2; h++) {
                uint32_t bh0[4], bh1[4];
                ldmx4(bh0, sBh + (br + (2 * h)     * 16) * SLD + kc + bc4);
                ldmx4(bh1, sBh + (br + (2 * h + 1) * 16) * SLD + kc + bc4);
                const int p0 = 4 * h, p1 = 4 * h + 2;
                mma_f16(acc[0][p0],     ah[0], bh0[0], bh0[1]);
                mma_f16(acc[0][p0 + 1], ah[0], bh0[2], bh0[3]);
                mma_f16(acc[1][p0],     ah[1], bh0[0], bh0[1]);
                mma_f16(acc[1][p0 + 1], ah[1], bh0[2], bh0[3]);
                mma_f16(acc[0][p1],     ah[0], bh1[0], bh1[1]);
                mma_f16(acc[0][p1 + 1], ah[0], bh1[2], bh1[3]);
                mma_f16(acc[1][p1],     ah[1], bh1[0], bh1[1]);
                mma_f16(acc[1][p1 + 1], ah[1], bh1[2], bh1[3]);
            }
        }
        __syncthreads();
        if (++b >= NSTAGE) b = 0;
    }

#pragma unroll
    for (int mf = 0; mf < 2; mf++) {
#pragma unroll
        for (int nf = 0; nf < 8; nf++) {
            const int r0 = bm + m0 + mf * 16 + g;
            const int r1 = r0 + 8;
            const int cc = bn + n0 + nf * 8 + tq * 2;
            const int Nd2 = N >> 1;
            float v0 = acc[mf][nf][0], v1 = acc[mf][nf][1];
            float v2 = acc[mf][nf][2], v3 = acc[mf][nf][3];

            if (EPI == 5) {
                const float2 a0 = *(const float2*)(aux1 + (size_t)r0 * N + cc);
                const float2 a1 = *(const float2*)(aux1 + (size_t)r1 * N + cc);
                v0 += a0.x; v1 += a0.y; v2 += a1.x; v3 += a1.y;
            }
            if (EPI == 6) {
                const float2 a0 = h2f2(aux1h[(size_t)r0 * Nd2 + (cc >> 1)]);
                const float2 a1 = h2f2(aux1h[(size_t)r1 * Nd2 + (cc >> 1)]);
                v0 += a0.x; v1 += a0.y; v2 += a1.x; v3 += a1.y;
            }
            if (EPI == 2 || EPI == 6) {
                const float2 bb = *(const float2*)(aux2 + cc);
                v0 += bb.x; v1 += bb.y; v2 += bb.x; v3 += bb.y;
            }
            if (EPI == 2) {
                v0 *= normcdff(v0); v1 *= normcdff(v1);
                v2 *= normcdff(v2); v3 *= normcdff(v3);
            }
            if (EPI == 2 || EPI == 4 || EPI == 5) {
                Chi[(size_t)r0 * Nd2 + (cc >> 1)] = hi2h(v0, v1);
                Chi[(size_t)r1 * Nd2 + (cc >> 1)] = hi2h(v2, v3);
            } else {
                *(float2*)(C + (size_t)r0 * N + cc) = make_float2(v0, v1);
                *(float2*)(C + (size_t)r1 * N + cc) = make_float2(v2, v3);
            }
        }
    }
}

// ---------------- attention: scores — register-blocked 4q x 8w, kk sliced x8 ----------------
// thread = (pb, ks): pb = qb*4 + wb (qb in [0,8): queries 4qb..4qb+3; wb in [0,4): w 8wb..8wb+7)
// ks in [0,8) slices kk. Partials reduced via bank-staggered smem.
__global__ __launch_bounds__(256) void attn_scores(
    const uint32_t* __restrict__ qkv, float* __restrict__ psc)
{
    __shared__ float sm[8 * 1057];               // 33824 B; also holds Ks/Qs during compute
    float (*Ks)[65] = (float(*)[65])sm;          // 63 x 65 = 4095 floats
    float (*Qs)[65] = (float(*)[65])(sm + 4160); // 32 x 65 = 2080 -> ends at 6240 < 8456

    const int tid = threadIdx.x;
    const int q0  = blockIdx.x * 32;
    const int b   = blockIdx.y;
    const int hs  = blockIdx.z;
    const int pb  = tid >> 3;
    const int ks  = tid & 7;
    const int qb4 = (pb >> 2) * 4;     // base query
    const int wb8 = (pb & 3) * 8;      // base w

    float acc[4][8];
#pragma unroll
    for (int d = 0; d < 4; d++)
#pragma unroll
        for (int e = 0; e < 8; e++) acc[d][e] = 0.f;

    for (int h0 = hs * 256; h0 < hs * 256 + 256; h0 += 64) {
        for (int idx = tid; idx < 63 * 16; idx += 256) {
            int r  = idx >> 4;
            int c  = (idx & 15) << 2;
            int jb = q0 - 31 + r;
            uint2 u = make_uint2(0u, 0u);
            if (jb >= 0)
                u = *(const uint2*)(qkv + (size_t)(b * Sn + jb) * QKV_LD + KOFF + ((h0 + c) >> 1));
            float2 f0 = h2f2(u.x), f1 = h2f2(u.y);
            Ks[r][c] = f0.x; Ks[r][c + 1] = f0.y; Ks[r][c + 2] = f1.x; Ks[r][c + 3] = f1.y;
        }
        for (int idx = tid; idx < 32 * 16; idx += 256) {
            int r = idx >> 4;
            int c = (idx & 15) << 2;
            uint2 u = *(const uint2*)(qkv + (size_t)(b * Sn + q0 + r) * QKV_LD + ((h0 + c) >> 1));
            float2 f0 = h2f2(u.x), f1 = h2f2(u.y);
            Qs[r][c] = f0.x; Qs[r][c + 1] = f0.y; Qs[r][c + 2] = f1.x; Qs[r][c + 3] = f1.y;
        }
        __syncthreads();

#pragma unroll
        for (int i = 0; i < 8; i++) {
            const int kk = ks * 8 + i;
            float qv[4], kv[11];
#pragma unroll
            for (int d = 0; d < 4; d++) qv[d] = Qs[qb4 + d][kk];
#pragma unroll
            for (int r = 0; r < 11; r++) kv[r] = Ks[qb4 + wb8 + r][kk];
#pragma unroll
            for (int d = 0; d < 4; d++)
#pragma unroll
                for (int e = 0; e < 8; e++)
                    acc[d][e] += qv[d] * kv[d + e];
        }
        __syncthreads();
    }

    // write kk-slice partials (slice stride 1057 keeps banks staggered)
#pragma unroll
    for (int d = 0; d < 4; d++)
#pragma unroll
        for (int e = 0; e < 8; e++)
            sm[ks * 1057 + (qb4 + d) * 33 + wb8 + e] = acc[d][e];
    __syncthreads();

    for (int t = tid; t < 1024; t += 256) {
        const int q = t >> 5, w = t & 31;
        float s = 0.f;
#pragma unroll
        for (int sl = 0; sl < 8; sl++) s += sm[sl * 1057 + q * 33 + w];
        psc[((size_t)hs * Mn + b * Sn + q0 + q) * 32 + w] = s;
    }
}

// ---------------- attention: softmax ----------------
__global__ __launch_bounds__(256) void attn_softmax(
    const float* __restrict__ psc, float* __restrict__ prob)
{
    const int warp = threadIdx.x >> 5, lane = threadIdx.x & 31;
    const int row  = blockIdx.x * 8 + warp;
    const int iq   = row & (Sn - 1);
    int wmin = 31 - iq; if (wmin < 0) wmin = 0;

    float s = 0.f;
#pragma unroll
    for (int hs = 0; hs < 4; hs++)
        s += psc[((size_t)hs * Mn + row) * 32 + lane];
    s *= (1.0f / 32.0f);

    const bool valid = (lane >= wmin);
    float m = valid ? s : -1e30f;
#pragma unroll
    for (int o = 16; o; o >>= 1) m = fmaxf(m, __shfl_xor_sync(0xffffffffu, m, o));
    float p = valid ? expf(s - m) : 0.f;
    float sum = p;
#pragma unroll
    for (int o = 16; o; o >>= 1) sum += __shfl_xor_sync(0xffffffffu, sum, o);
    prob[(size_t)row * 32 + lane] = p / sum;
}

// ---------------- attention: PV — 2 queries x 8 cols per thread, row reuse ----------------
// thread = (qh, cg): queries 2qh, 2qh+1; cols cg*8..cg*8+7 of the 128-col chunk.
// Walk 33 V rows; row qa+rr serves (qa, w=rr) and (qa+1, w=rr-1).
__global__ __launch_bounds__(256, 2) void attn_pv(
    const uint32_t* __restrict__ qkv, const float* __restrict__ prob,
    uint32_t* __restrict__ Ohi)
{
    __shared__ float Vs[63][132];

    const int tid = threadIdx.x;
    const int q0  = blockIdx.x * 32;
    const int b   = blockIdx.y;
    const int h0  = blockIdx.z * 128;
    const int qh  = tid >> 4;
    const int cg  = tid & 15;
    const int qa  = 2 * qh;

    for (int idx = tid; idx < 63 * 32; idx += 256) {
        int r  = idx >> 5;
        int c  = (idx & 31) << 2;
        int jb = q0 - 31 + r;
        uint2 u = make_uint2(0u, 0u);
        if (jb >= 0)
            u = *(const uint2*)(qkv + (size_t)(b * Sn + jb) * QKV_LD + VOFF + ((h0 + c) >> 1));
        float2 f0 = h2f2(u.x), f1 = h2f2(u.y);
        Vs[r][c] = f0.x; Vs[r][c + 1] = f0.y; Vs[r][c + 2] = f1.x; Vs[r][c + 3] = f1.y;
    }

    float pa[32], pb_[32];
    {
        const float* pra = prob + (size_t)(b * Sn + q0 + qa) * 32;
        const float* prb = pra + 32;
#pragma unroll
        for (int w = 0; w < 32; w++) { pa[w] = pra[w]; pb_[w] = prb[w]; }
    }
    __syncthreads();

    float oa[8], ob[8];
#pragma unroll
    for (int c = 0; c < 8; c++) { oa[c] = 0.f; ob[c] = 0.f; }

#pragma unroll
    for (int rr = 0; rr < 33; rr++) {
        const float* vr = &Vs[qa + rr][cg * 8];
        float v[8];
        *(float4*)(v)     = *(const float4*)(vr);
        *(float4*)(v + 4) = *(const float4*)(vr + 4);
        if (rr < 32) {
            const float p = pa[rr];
#pragma unroll
            for (int c = 0; c < 8; c++) oa[c] += p * v[c];
        }
        if (rr >= 1) {
            const float p = pb_[rr - 1];
#pragma unroll
            for (int c = 0; c < 8; c++) ob[c] += p * v[c];
        }
    }

    const size_t ra = (size_t)(b * Sn + q0 + qa) * (Hn / 2) + (h0 >> 1) + cg * 4;
    const size_t rb = ra + (Hn / 2);
#pragma unroll
    for (int c = 0; c < 8; c += 2) {
        Ohi[ra + (c >> 1)] = hi2h(oa[c], oa[c + 1]);
        Ohi[rb + (c >> 1)] = hi2h(ob[c], ob[c + 1]);
    }
}

// ---------------- layernorm: single-pass, fp16 in/out ----------------
__global__ __launch_bounds__(256) void ln_kernel(
    const uint32_t* __restrict__ Xh, const float* __restrict__ w,
    const float* __restrict__ bb, uint32_t* __restrict__ Yhi)
{
    const int row = blockIdx.x;
    const int tid = threadIdx.x;
    const uint2 u = *(const uint2*)(Xh + (size_t)row * (Hn / 2) + tid * 2);
    const float2 f0 = h2f2(u.x), f1 = h2f2(u.y);

    float s  = f0.x + f0.y + f1.x + f1.y;
    float ss = f0.x * f0.x + f0.y * f0.y + f1.x * f1.x + f1.y * f1.y;

    __shared__ float red[64];
#pragma unroll
    for (int o = 16; o; o >>= 1) {
        s  += __shfl_down_sync(0xffffffffu, s,  o);
        ss += __shfl_down_sync(0xffffffffu, ss, o);
    }
    const int warp = tid >> 5, lane = tid & 31;
    if (lane == 0) { red[warp] = s; red[32 + warp] = ss; }
    __syncthreads();
    if (tid == 0) {
        float S = 0.f, SS = 0.f;
        for (int i = 0; i < 8; i++) { S += red[i]; SS += red[32 + i]; }
        red[0] = S; red[1] = SS;
    }
    __syncthreads();
    const float mu   = red[0] * (1.0f / Hn);
    const float var  = red[1] * (1.0f / Hn) - mu * mu;
    const float rstd = rsqrtf(var + 1e-5f);

    const float4 wv = *(const float4*)(w  + tid * 4);
    const float4 bv = *(const float4*)(bb + tid * 4);
    float y0 = (f0.x - mu) * rstd * wv.x + bv.x;
    float y1 = (f0.y - mu) * rstd * wv.y + bv.y;
    float y2 = (f1.x - mu) * rstd * wv.z + bv.z;
    float y3 = (f1.y - mu) * rstd * wv.w + bv.w;
    *(uint2*)(Yhi + (size_t)row * (Hn / 2) + tid * 2) = make_uint2(hi2h(y0, y1), hi2h(y2, y3));
}

// ---------------- launch ----------------
extern "C" void kernel_launch(void* const* d_in, const int* in_sizes, int n_in,
                              void* d_out, int out_size)
{
    const float* x   = (const float*)d_in[0];
    const float* Wq  = (const float*)d_in[1];
    const float* Wk  = (const float*)d_in[2];
    const float* Wv  = (const float*)d_in[3];
    const float* Wo  = (const float*)d_in[4];
    const float* lnw = (const float*)d_in[5];
    const float* lnb = (const float*)d_in[6];
    const float* W1  = (const float*)d_in[7];
    const float* b1  = (const float*)d_in[8];
    const float* W2  = (const float*)d_in[9];
    const float* b2  = (const float*)d_in[10];
    float* out = (float*)d_out;

    uint32_t *xh, *wqkvh, *woh, *w1h, *w2h, *qkvh, *ath, *drh, *lnh, *h1h;
    float *psc, *prob;
    cudaGetSymbolAddress((void**)&xh,    g_x_h);
    cudaGetSymbolAddress((void**)&wqkvh, g_wqkv_h);
    cudaGetSymbolAddress((void**)&woh,   g_wo_h);
    cudaGetSymbolAddress((void**)&w1h,   g_w1_h);
    cudaGetSymbolAddress((void**)&w2h,   g_w2_h);
    cudaGetSymbolAddress((void**)&qkvh,  g_qkv_h);
    cudaGetSymbolAddress((void**)&ath,   g_at_h);
    cudaGetSymbolAddress((void**)&drh,   g_dr_h);
    cudaGetSymbolAddress((void**)&lnh,   g_ln_h);
    cudaGetSymbolAddress((void**)&h1h,   g_h1_h);
    cudaGetSymbolAddress((void**)&psc,   g_psc);
    cudaGetSymbolAddress((void**)&prob,  g_prob);

    cudaFuncSetAttribute(gemm_mma<2>, cudaFuncAttributeMaxDynamicSharedMemorySize, GEMM_SMEM);
    cudaFuncSetAttribute(gemm_mma<4>, cudaFuncAttributeMaxDynamicSharedMemorySize, GEMM_SMEM);
    cudaFuncSetAttribute(gemm_mma<5>, cudaFuncAttributeMaxDynamicSharedMemorySize, GEMM_SMEM);
    cudaFuncSetAttribute(gemm_mma<6>, cudaFuncAttributeMaxDynamicSharedMemorySize, GEMM_SMEM);

    // fused conversion (one launch)
    const int nX = Mn * Hn / 4;
    const int nW = Hn * Hn / 4;
    const int nH = Hn * Hn / 8;
    const int total = nX + 4 * nW + 2 * nH;
    conv_all<<<(total + 255) / 256, 256>>>(
        x,  xh, nX,
        Wq, wqkvh,              nW,
        Wk, wqkvh + 1 * nW * 2, nW,
        Wv, wqkvh + 2 * nW * 2, nW,
        Wo, woh, nW,
        W1, w1h, nH,
        W2, w2h, nH);

    dim3 gridQKV(3 * Hn / BN,   Mn / BM);   // (24, 64)
    dim3 gridH  (Hn / BN,       Mn / BM);   // (8, 64)
    dim3 gridH2 ((Hn / 2) / BN, Mn / BM);   // (4, 64)

    // fused QKV projection -> packed fp16 [q|k|v] rows
    gemm_mma<4><<<gridQKV, 256, GEMM_SMEM>>>(xh, wqkvh, nullptr, qkvh, Mn, 3 * Hn, Hn, nullptr, nullptr, nullptr);

    // banded attention
    attn_scores <<<dim3(Sn / 32, Bn, 4), 256>>>(qkvh, psc);
    attn_softmax<<<Mn / 8, 256>>>(psc, prob);
    attn_pv     <<<dim3(Sn / 32, Bn, 8), 256>>>(qkvh, prob, ath);

    // draft = fp16(x + attn @ Wo^T)
    gemm_mma<5><<<gridH, 256, GEMM_SMEM>>>(ath, woh, nullptr, drh, Mn, Hn, Hn, x, nullptr, nullptr);

    // layernorm (fp16 in/out)
    ln_kernel<<<Mn, 256>>>(drh, lnw, lnb, lnh);

    // h1 = gelu(ln @ W1^T + b1) -> fp16 pairs
    gemm_mma<2><<<gridH2, 256, GEMM_SMEM>>>(lnh, w1h, nullptr, h1h, Mn, Hn / 2, Hn, nullptr, b1, nullptr);

    // out = draft(fp16) + h1 @ W2^T + b2  (fp32)
    gemm_mma<6><<<gridH, 256, GEMM_SMEM>>>(h1h, w2h, out, nullptr, Mn, Hn, Hn / 2, nullptr, b2, drh);
}

// round 16
// speedup vs baseline: 1.3718x; 1.1362x over previous
#include <cuda_runtime.h>
#include <cuda_fp16.h>
#include <math.h>
#include <stdint.h>

#define Bn   2
#define Sn   4096
#define Hn   1024
#define Mn   (Bn * Sn)       // 8192 rows
#define WIN  32

// ---------------- scratch (no allocations allowed) ----------------
__device__ uint32_t g_x_h   [Mn * Hn / 2];
__device__ uint32_t g_wqkv_h[3 * Hn * Hn / 2];   // rows: [Wq | Wk | Wv]
__device__ uint32_t g_wo_h  [Hn * Hn / 2];
__device__ uint32_t g_w1_h  [(Hn / 2) * Hn / 2];
__device__ uint32_t g_w2_h  [Hn * (Hn / 2) / 2];
__device__ uint32_t g_qkv_h [Mn * 3 * Hn / 2];   // per row: [q(512u32) | k(512) | v(512)]
__device__ uint32_t g_at_h  [Mn * Hn / 2];
__device__ uint32_t g_dr_h  [Mn * Hn / 2];       // draft, fp16 pairs
__device__ uint32_t g_ln_h  [Mn * Hn / 2];
__device__ uint32_t g_h1_h  [Mn * Hn / 4];
__device__ float g_psc [4 * Mn * 32];
__device__ float g_prob[Mn * 32];

#define QKV_LD (3 * Hn / 2)   // 1536 u32 per row
#define KOFF   (Hn / 2)       // 512
#define VOFF   (Hn)           // 1024

// ---------------- fp16 helpers ----------------
__device__ __forceinline__ uint32_t pack2_h(__half a, __half b) {
    __half2 t; t.x = a; t.y = b;
    return *(uint32_t*)&t;
}
__device__ __forceinline__ uint32_t hi2h(float x, float y) {
    return pack2_h(__float2half_rn(x), __float2half_rn(y));
}
__device__ __forceinline__ float2 h2f2(uint32_t u) {
    __half2 h = *(__half2*)&u;
    return __half22float2(h);
}
__device__ __forceinline__ void mma_f16(float c[4], const uint32_t a[4], uint32_t b0, uint32_t b1) {
    asm("mma.sync.aligned.m16n8k16.row.col.f32.f16.f16.f32 "
        "{%0,%1,%2,%3}, {%4,%5,%6,%7}, {%8,%9}, {%0,%1,%2,%3};\n"
        : "+f"(c[0]), "+f"(c[1]), "+f"(c[2]), "+f"(c[3])
        : "r"(a[0]), "r"(a[1]), "r"(a[2]), "r"(a[3]), "r"(b0), "r"(b1));
}
__device__ __forceinline__ void ldmx4(uint32_t r[4], const uint32_t* p) {
    uint32_t a = (uint32_t)__cvta_generic_to_shared(p);
    asm volatile("ldmatrix.sync.aligned.m8n8.x4.shared.b16 {%0,%1,%2,%3}, [%4];"
        : "=r"(r[0]), "=r"(r[1]), "=r"(r[2]), "=r"(r[3]) : "r"(a));
}
__device__ __forceinline__ void cp16(uint32_t sdst, const void* gsrc) {
    asm volatile("cp.async.cg.shared.global [%0], [%1], 16;" :: "r"(sdst), "l"(gsrc));
}
__device__ __forceinline__ void cp4(uint32_t sdst, const void* gsrc) {
    asm volatile("cp.async.ca.shared.global [%0], [%1], 4;" :: "r"(sdst), "l"(gsrc));
}
#define CP_COMMIT() asm volatile("cp.async.commit_group;" ::: "memory")

// ---------------- fused conversion ----------------
__global__ __launch_bounds__(256) void conv_all(
    const float* s0, uint32_t* d0, int n0,
    const float* s1, uint32_t* d1, int n1,
    const float* s2, uint32_t* d2, int n2,
    const float* s3, uint32_t* d3, int n3,
    const float* s4, uint32_t* d4, int n4c,
    const float* s5, uint32_t* d5, int n5,
    const float* s6, uint32_t* d6, int n6)
{
    int i = blockIdx.x * 256 + threadIdx.x;
    const float* s; uint32_t* d;
    if      (i < n0)                        { s = s0; d = d0; }
    else if ((i -= n0) < n1)                { s = s1; d = d1; }
    else if ((i -= n1) < n2)                { s = s2; d = d2; }
    else if ((i -= n2) < n3)                { s = s3; d = d3; }
    else if ((i -= n3) < n4c)               { s = s4; d = d4; }
    else if ((i -= n4c) < n5)               { s = s5; d = d5; }
    else if ((i -= n5) < n6)                { s = s6; d = d6; }
    else return;
    float4 v = ((const float4*)s)[i];
    ((uint2*)d)[i] = make_uint2(hi2h(v.x, v.y), hi2h(v.z, v.w));
}

// ---------------- GEMM (unchanged from R15) ----------------
#define BM 128
#define BN 128
#define SLD 20
#define MATW (BM * SLD)
#define STGW (2 * MATW)
#define NSTAGE 3
#define GEMM_SMEM (NSTAGE * STGW * 4)

template<int EPI>
__global__ __launch_bounds__(256, 2) void gemm_mma(
    const uint32_t* __restrict__ Ahg, const uint32_t* __restrict__ Bhg,
    float* __restrict__ C, uint32_t* __restrict__ Chi,
    int M, int N, int K,
    const float* __restrict__ aux1, const float* __restrict__ aux2,
    const uint32_t* __restrict__ aux1h)
{
    extern __shared__ uint32_t smem[];

    const int Kd2  = K >> 1;
    const int nt   = Kd2 >> 4;
    const int tid  = threadIdx.x;
    const int wid  = tid >> 5;
    const int lane = tid & 31;
    const int g    = lane >> 2;
    const int tq   = lane & 3;

    const int bm = blockIdx.y * BM;
    const int bn = blockIdx.x * BN;
    const int m0 = (wid & 3) * 32;
    const int n0 = (wid >> 2) * 64;

    const int sr0 = tid >> 2,         sc0 = (tid & 3) << 2;
    const int sr1 = (tid + 256) >> 2, sc1 = ((tid + 256) & 3) << 2;
    const uint32_t smem_base = (uint32_t)__cvta_generic_to_shared(smem);

    float acc[2][8][4];
#pragma unroll
    for (int i = 0; i < 2; i++)
#pragma unroll
        for (int j = 0; j < 8; j++)
#pragma unroll
            for (int r = 0; r < 4; r++) acc[i][j][r] = 0.f;

    const int ar  = m0 + ((lane & 15) >> 3) * 8 + (lane & 7);
    const int ac4 = (lane >> 4) * 4;
    const int br  = n0 + (lane >> 4) * 8 + (lane & 7);
    const int bc4 = ((lane & 15) >> 3) * 4;

    auto stage = [&](int k, int b) {
        const uint32_t sbase = smem_base + (uint32_t)(b * STGW) * 4u;
        const int koff = k * 16;
        {
            const size_t ga = (size_t)(bm + sr0) * Kd2 + koff + sc0;
            const size_t gb = (size_t)(bn + sr0) * Kd2 + koff + sc0;
            const uint32_t so = (uint32_t)(sr0 * SLD + sc0) * 4u;
            cp16(sbase + 0 * MATW * 4 + so, Ahg + ga);
            cp16(sbase + 1 * MATW * 4 + so, Bhg + gb);
        }
        {
            const size_t ga = (size_t)(bm + sr1) * Kd2 + koff + sc1;
            const size_t gb = (size_t)(bn + sr1) * Kd2 + koff + sc1;
            const uint32_t so = (uint32_t)(sr1 * SLD + sc1) * 4u;
            cp16(sbase + 0 * MATW * 4 + so, Ahg + ga);
            cp16(sbase + 1 * MATW * 4 + so, Bhg + gb);
        }
    };

    stage(0, 0);
    CP_COMMIT();
    if (nt > 1) { stage(1, 1); CP_COMMIT(); }

    int b = 0;
    for (int k = 0; k < nt; k++) {
        if (k + 2 < nt) {
            int bs = b + 2; if (bs >= NSTAGE) bs -= NSTAGE;
            stage(k + 2, bs);
            CP_COMMIT();
            asm volatile("cp.async.wait_group 2;" ::: "memory");
        } else if (k + 1 < nt) {
            asm volatile("cp.async.wait_group 1;" ::: "memory");
        } else {
            asm volatile("cp.async.wait_group 0;" ::: "memory");
        }
        __syncthreads();

        const uint32_t* sAh = smem + b * STGW + 0 * MATW;
        const uint32_t* sBh = smem + b * STGW + 1 * MATW;

#pragma unroll
        for (int kc = 0; kc < 16; kc += 8) {
            uint32_t ah[2][4];
            ldmx4(ah[0], sAh + (ar     ) * SLD + kc + ac4);
            ldmx4(ah[1], sAh + (ar + 16) * SLD + kc + ac4);
#pragma unroll
            for (int h = 0; h < 2; h++) {
                uint32_t bh0[4], bh1[4];
                ldmx4(bh0, sBh + (br + (2 * h)     * 16) * SLD + kc + bc4);
                ldmx4(bh1, sBh + (br + (2 * h + 1) * 16) * SLD + kc + bc4);
                const int p0 = 4 * h, p1 = 4 * h + 2;
                mma_f16(acc[0][p0],     ah[0], bh0[0], bh0[1]);
                mma_f16(acc[0][p0 + 1], ah[0], bh0[2], bh0[3]);
                mma_f16(acc[1][p0],     ah[1], bh0[0], bh0[1]);
                mma_f16(acc[1][p0 + 1], ah[1], bh0[2], bh0[3]);
                mma_f16(acc[0][p1],     ah[0], bh1[0], bh1[1]);
                mma_f16(acc[0][p1 + 1], ah[0], bh1[2], bh1[3]);
                mma_f16(acc[1][p1],     ah[1], bh1[0], bh1[1]);
                mma_f16(acc[1][p1 + 1], ah[1], bh1[2], bh1[3]);
            }
        }
        __syncthreads();
        if (++b >= NSTAGE) b = 0;
    }

#pragma unroll
    for (int mf = 0; mf < 2; mf++) {
#pragma unroll
        for (int nf = 0; nf < 8; nf++) {
            const int r0 = bm + m0 + mf * 16 + g;
            const int r1 = r0 + 8;
            const int cc = bn + n0 + nf * 8 + tq * 2;
            const int Nd2 = N >> 1;
            float v0 = acc[mf][nf][0], v1 = acc[mf][nf][1];
            float v2 = acc[mf][nf][2], v3 = acc[mf][nf][3];

            if (EPI == 5) {
                const float2 a0 = *(const float2*)(aux1 + (size_t)r0 * N + cc);
                const float2 a1 = *(const float2*)(aux1 + (size_t)r1 * N + cc);
                v0 += a0.x; v1 += a0.y; v2 += a1.x; v3 += a1.y;
            }
            if (EPI == 6) {
                const float2 a0 = h2f2(aux1h[(size_t)r0 * Nd2 + (cc >> 1)]);
                const float2 a1 = h2f2(aux1h[(size_t)r1 * Nd2 + (cc >> 1)]);
                v0 += a0.x; v1 += a0.y; v2 += a1.x; v3 += a1.y;
            }
            if (EPI == 2 || EPI == 6) {
                const float2 bb = *(const float2*)(aux2 + cc);
                v0 += bb.x; v1 += bb.y; v2 += bb.x; v3 += bb.y;
            }
            if (EPI == 2) {
                v0 *= normcdff(v0); v1 *= normcdff(v1);
                v2 *= normcdff(v2); v3 *= normcdff(v3);
            }
            if (EPI == 2 || EPI == 4 || EPI == 5) {
                Chi[(size_t)r0 * Nd2 + (cc >> 1)] = hi2h(v0, v1);
                Chi[(size_t)r1 * Nd2 + (cc >> 1)] = hi2h(v2, v3);
            } else {
                *(float2*)(C + (size_t)r0 * N + cc) = make_float2(v0, v1);
                *(float2*)(C + (size_t)r1 * N + cc) = make_float2(v2, v3);
            }
        }
    }
}

// ---------------- attention: scores — fp16-pair smem, cp.async double-buffered ----------------
// thread = (pb, ks): qb4 = (pb>>2)*4 queries, wb8 = (pb&3)*8 w's; ks slices u32 cols.
// smem: Kb[2][63][33] u32 + Qb[2][32][33] u32, aliased later by 8x1057 float reduction.
#define SC_SMEM 33824   // bytes = 8*1057 floats (>= 6270 u32 fill region)

__global__ __launch_bounds__(256) void attn_scores(
    const uint32_t* __restrict__ qkv, float* __restrict__ psc)
{
    extern __shared__ uint32_t dsm[];
    uint32_t* Kb = dsm;                    // [2][63][33]
    uint32_t* Qb = dsm + 2 * 63 * 33;      // [2][32][33]
    float*    red = (float*)dsm;           // aliases fill region (used after final sync)

    const int tid = threadIdx.x;
    const int q0  = blockIdx.x * 32;
    const int b   = blockIdx.y;
    const int hs  = blockIdx.z;
    const int pb  = tid >> 3;
    const int ks  = tid & 7;
    const int qb4 = (pb >> 2) * 4;
    const int wb8 = (pb & 3) * 8;
    const uint32_t smem_base = (uint32_t)__cvta_generic_to_shared(dsm);

    // pre-zero boundary K rows (rows 0..30 invalid when q0 == 0), both buffers
    if (blockIdx.x == 0) {
        for (int i = tid; i < 31 * 33; i += 256) {
            Kb[i] = 0u;
            Kb[63 * 33 + i] = 0u;
        }
    }
    __syncthreads();

    auto fill = [&](int ci, int buf) {
        const int h0u = hs * 128 + ci * 32;            // u32 offset into H
        const uint32_t kbase = smem_base + (uint32_t)(buf * 63 * 33) * 4u;
        const uint32_t qbase = smem_base + (uint32_t)(2 * 63 * 33 + buf * 32 * 33) * 4u;
        for (int idx = tid; idx < 63 * 32; idx += 256) {
            const int r = idx >> 5, c = idx & 31;
            const int jb = q0 - 31 + r;
            if (jb >= 0)
                cp4(kbase + (uint32_t)(r * 33 + c) * 4u,
                    qkv + (size_t)(b * Sn + jb) * QKV_LD + KOFF + h0u + c);
        }
        for (int idx = tid; idx < 32 * 32; idx += 256) {
            const int r = idx >> 5, c = idx & 31;
            cp4(qbase + (uint32_t)(r * 33 + c) * 4u,
                qkv + (size_t)(b * Sn + q0 + r) * QKV_LD + h0u + c);
        }
    };

    float acc[4][8];
#pragma unroll
    for (int d = 0; d < 4; d++)
#pragma unroll
        for (int e = 0; e < 8; e++) acc[d][e] = 0.f;

    fill(0, 0);
    CP_COMMIT();

    for (int ci = 0; ci < 4; ci++) {
        const int buf = ci & 1;
        if (ci + 1 < 4) {
            fill(ci + 1, buf ^ 1);
            CP_COMMIT();
            asm volatile("cp.async.wait_group 1;" ::: "memory");
        } else {
            asm volatile("cp.async.wait_group 0;" ::: "memory");
        }
        __syncthreads();

        const uint32_t* Ks = Kb + buf * 63 * 33;
        const uint32_t* Qs = Qb + buf * 32 * 33;
#pragma unroll
        for (int i = 0; i < 4; i++) {
            const int kc = ks * 4 + i;
            float2 qv[4];
#pragma unroll
            for (int d = 0; d < 4; d++) qv[d] = h2f2(Qs[(qb4 + d) * 33 + kc]);
            float2 kv[11];
#pragma unroll
            for (int r = 0; r < 11; r++) kv[r] = h2f2(Ks[(qb4 + wb8 + r) * 33 + kc]);
#pragma unroll
            for (int d = 0; d < 4; d++)
#pragma unroll
                for (int e = 0; e < 8; e++)
                    acc[d][e] += qv[d].x * kv[d + e].x + qv[d].y * kv[d + e].y;
        }
        __syncthreads();
    }

    // kk-slice partial reduction (red aliases fill region; safe after last sync)
#pragma unroll
    for (int d = 0; d < 4; d++)
#pragma unroll
        for (int e = 0; e < 8; e++)
            red[ks * 1057 + (qb4 + d) * 33 + wb8 + e] = acc[d][e];
    __syncthreads();

    for (int t = tid; t < 1024; t += 256) {
        const int q = t >> 5, w = t & 31;
        float s = 0.f;
#pragma unroll
        for (int sl = 0; sl < 8; sl++) s += red[sl * 1057 + q * 33 + w];
        psc[((size_t)hs * Mn + b * Sn + q0 + q) * 32 + w] = s;
    }
}

// ---------------- attention: softmax ----------------
__global__ __launch_bounds__(256) void attn_softmax(
    const float* __restrict__ psc, float* __restrict__ prob)
{
    const int warp = threadIdx.x >> 5, lane = threadIdx.x & 31;
    const int row  = blockIdx.x * 8 + warp;
    const int iq   = row & (Sn - 1);
    int wmin = 31 - iq; if (wmin < 0) wmin = 0;

    float s = 0.f;
#pragma unroll
    for (int hs = 0; hs < 4; hs++)
        s += psc[((size_t)hs * Mn + row) * 32 + lane];
    s *= (1.0f / 32.0f);

    const bool valid = (lane >= wmin);
    float m = valid ? s : -1e30f;
#pragma unroll
    for (int o = 16; o; o >>= 1) m = fmaxf(m, __shfl_xor_sync(0xffffffffu, m, o));
    float p = valid ? expf(s - m) : 0.f;
    float sum = p;
#pragma unroll
    for (int o = 16; o; o >>= 1) sum += __shfl_xor_sync(0xffffffffu, sum, o);
    prob[(size_t)row * 32 + lane] = p / sum;
}

// ---------------- attention: PV — fp16-pair smem, cp.async fill, 2q x 8col ----------------
__global__ __launch_bounds__(256, 2) void attn_pv(
    const uint32_t* __restrict__ qkv, const float* __restrict__ prob,
    uint32_t* __restrict__ Ohi)
{
    __shared__ uint32_t Vs[63][68];    // 64 u32 cols (128 halves) + 4 pad; rows 16B-aligned

    const int tid = threadIdx.x;
    const int q0  = blockIdx.x * 32;
    const int b   = blockIdx.y;
    const int h0u = blockIdx.z * 64;   // u32 offset into H
    const int qh  = tid >> 4;
    const int cg  = tid & 15;
    const int qa  = 2 * qh;
    const uint32_t vbase = (uint32_t)__cvta_generic_to_shared(&Vs[0][0]);

    // pre-zero boundary rows, then async fill valid rows
    if (blockIdx.x == 0) {
        for (int i = tid; i < 31 * 68; i += 256)
            ((uint32_t*)Vs)[i] = 0u;
    }
    __syncthreads();

    for (int idx = tid; idx < 63 * 16; idx += 256) {
        const int r = idx >> 4, c4 = (idx & 15) << 2;
        const int jb = q0 - 31 + r;
        if (jb >= 0)
            cp16(vbase + (uint32_t)(r * 68 + c4) * 4u,
                 qkv + (size_t)(b * Sn + jb) * QKV_LD + VOFF + h0u + c4);
    }
    CP_COMMIT();

    // overlap: load probabilities while the fill streams in
    float pa[32], pb_[32];
    {
        const float* pra = prob + (size_t)(b * Sn + q0 + qa) * 32;
        const float* prb = pra + 32;
#pragma unroll
        for (int w = 0; w < 32; w++) { pa[w] = pra[w]; pb_[w] = prb[w]; }
    }
    asm volatile("cp.async.wait_group 0;" ::: "memory");
    __syncthreads();

    float oa[8], ob[8];
#pragma unroll
    for (int c = 0; c < 8; c++) { oa[c] = 0.f; ob[c] = 0.f; }

#pragma unroll
    for (int rr = 0; rr < 33; rr++) {
        const uint4 vv = *(const uint4*)&Vs[qa + rr][cg * 4];
        const float2 f0 = h2f2(vv.x), f1 = h2f2(vv.y);
        const float2 f2 = h2f2(vv.z), f3 = h2f2(vv.w);
        float v[8] = {f0.x, f0.y, f1.x, f1.y, f2.x, f2.y, f3.x, f3.y};
        if (rr < 32) {
            const float p = pa[rr];
#pragma unroll
            for (int c = 0; c < 8; c++) oa[c] += p * v[c];
        }
        if (rr >= 1) {
            const float p = pb_[rr - 1];
#pragma unroll
            for (int c = 0; c < 8; c++) ob[c] += p * v[c];
        }
    }

    const size_t ra = (size_t)(b * Sn + q0 + qa) * (Hn / 2) + h0u + cg * 4;
    const size_t rb = ra + (Hn / 2);
#pragma unroll
    for (int c = 0; c < 8; c += 2) {
        Ohi[ra + (c >> 1)] = hi2h(oa[c], oa[c + 1]);
        Ohi[rb + (c >> 1)] = hi2h(ob[c], ob[c + 1]);
    }
}

// ---------------- layernorm: single-pass, fp16 in/out ----------------
__global__ __launch_bounds__(256) void ln_kernel(
    const uint32_t* __restrict__ Xh, const float* __restrict__ w,
    const float* __restrict__ bb, uint32_t* __restrict__ Yhi)
{
    const int row = blockIdx.x;
    const int tid = threadIdx.x;
    const uint2 u = *(const uint2*)(Xh + (size_t)row * (Hn / 2) + tid * 2);
    const float2 f0 = h2f2(u.x), f1 = h2f2(u.y);

    float s  = f0.x + f0.y + f1.x + f1.y;
    float ss = f0.x * f0.x + f0.y * f0.y + f1.x * f1.x + f1.y * f1.y;

    __shared__ float red[64];
#pragma unroll
    for (int o = 16; o; o >>= 1) {
        s  += __shfl_down_sync(0xffffffffu, s,  o);
        ss += __shfl_down_sync(0xffffffffu, ss, o);
    }
    const int warp = tid >> 5, lane = tid & 31;
    if (lane == 0) { red[warp] = s; red[32 + warp] = ss; }
    __syncthreads();
    if (tid == 0) {
        float S = 0.f, SS = 0.f;
        for (int i = 0; i < 8; i++) { S += red[i]; SS += red[32 + i]; }
        red[0] = S; red[1] = SS;
    }
    __syncthreads();
    const float mu   = red[0] * (1.0f / Hn);
    const float var  = red[1] * (1.0f / Hn) - mu * mu;
    const float rstd = rsqrtf(var + 1e-5f);

    const float4 wv = *(const float4*)(w  + tid * 4);
    const float4 bv = *(const float4*)(bb + tid * 4);
    float y0 = (f0.x - mu) * rstd * wv.x + bv.x;
    float y1 = (f0.y - mu) * rstd * wv.y + bv.y;
    float y2 = (f1.x - mu) * rstd * wv.z + bv.z;
    float y3 = (f1.y - mu) * rstd * wv.w + bv.w;
    *(uint2*)(Yhi + (size_t)row * (Hn / 2) + tid * 2) = make_uint2(hi2h(y0, y1), hi2h(y2, y3));
}

// ---------------- launch ----------------
extern "C" void kernel_launch(void* const* d_in, const int* in_sizes, int n_in,
                              void* d_out, int out_size)
{
    const float* x   = (const float*)d_in[0];
    const float* Wq  = (const float*)d_in[1];
    const float* Wk  = (const float*)d_in[2];
    const float* Wv  = (const float*)d_in[3];
    const float* Wo  = (const float*)d_in[4];
    const float* lnw = (const float*)d_in[5];
    const float* lnb = (const float*)d_in[6];
    const float* W1  = (const float*)d_in[7];
    const float* b1  = (const float*)d_in[8];
    const float* W2  = (const float*)d_in[9];
    const float* b2  = (const float*)d_in[10];
    float* out = (float*)d_out;

    uint32_t *xh, *wqkvh, *woh, *w1h, *w2h, *qkvh, *ath, *drh, *lnh, *h1h;
    float *psc, *prob;
    cudaGetSymbolAddress((void**)&xh,    g_x_h);
    cudaGetSymbolAddress((void**)&wqkvh, g_wqkv_h);
    cudaGetSymbolAddress((void**)&woh,   g_wo_h);
    cudaGetSymbolAddress((void**)&w1h,   g_w1_h);
    cudaGetSymbolAddress((void**)&w2h,   g_w2_h);
    cudaGetSymbolAddress((void**)&qkvh,  g_qkv_h);
    cudaGetSymbolAddress((void**)&ath,   g_at_h);
    cudaGetSymbolAddress((void**)&drh,   g_dr_h);
    cudaGetSymbolAddress((void**)&lnh,   g_ln_h);
    cudaGetSymbolAddress((void**)&h1h,   g_h1_h);
    cudaGetSymbolAddress((void**)&psc,   g_psc);
    cudaGetSymbolAddress((void**)&prob,  g_prob);

    cudaFuncSetAttribute(gemm_mma<2>, cudaFuncAttributeMaxDynamicSharedMemorySize, GEMM_SMEM);
    cudaFuncSetAttribute(gemm_mma<4>, cudaFuncAttributeMaxDynamicSharedMemorySize, GEMM_SMEM);
    cudaFuncSetAttribute(gemm_mma<5>, cudaFuncAttributeMaxDynamicSharedMemorySize, GEMM_SMEM);
    cudaFuncSetAttribute(gemm_mma<6>, cudaFuncAttributeMaxDynamicSharedMemorySize, GEMM_SMEM);

    // fused conversion (one launch)
    const int nX = Mn * Hn / 4;
    const int nW = Hn * Hn / 4;
    const int nH = Hn * Hn / 8;
    const int total = nX + 4 * nW + 2 * nH;
    conv_all<<<(total + 255) / 256, 256>>>(
        x,  xh, nX,
        Wq, wqkvh,              nW,
        Wk, wqkvh + 1 * nW * 2, nW,
        Wv, wqkvh + 2 * nW * 2, nW,
        Wo, woh, nW,
        W1, w1h, nH,
        W2, w2h, nH);

    dim3 gridQKV(3 * Hn / BN,   Mn / BM);   // (24, 64)
    dim3 gridH  (Hn / BN,       Mn / BM);   // (8, 64)
    dim3 gridH2 ((Hn / 2) / BN, Mn / BM);   // (4, 64)

    // fused QKV projection -> packed fp16 [q|k|v] rows
    gemm_mma<4><<<gridQKV, 256, GEMM_SMEM>>>(xh, wqkvh, nullptr, qkvh, Mn, 3 * Hn, Hn, nullptr, nullptr, nullptr);

    // banded attention
    attn_scores <<<dim3(Sn / 32, Bn, 4), 256, SC_SMEM>>>(qkvh, psc);
    attn_softmax<<<Mn / 8, 256>>>(psc, prob);
    attn_pv     <<<dim3(Sn / 32, Bn, 8), 256>>>(qkvh, prob, ath);

    // draft = fp16(x + attn @ Wo^T)
    gemm_mma<5><<<gridH, 256, GEMM_SMEM>>>(ath, woh, nullptr, drh, Mn, Hn, Hn, x, nullptr, nullptr);

    // layernorm (fp16 in/out)
    ln_kernel<<<Mn, 256>>>(drh, lnw, lnb, lnh);

    // h1 = gelu(ln @ W1^T + b1) -> fp16 pairs
    gemm_mma<2><<<gridH2, 256, GEMM_SMEM>>>(lnh, w1h, nullptr, h1h, Mn, Hn / 2, Hn, nullptr, b1, nullptr);

    // out = draft(fp16) + h1 @ W2^T + b2  (fp32)
    gemm_mma<6><<<gridH, 256, GEMM_SMEM>>>(h1h, w2h, out, nullptr, Mn, Hn, Hn / 2, nullptr, b2, drh);
}

// round 17
// speedup vs baseline: 1.5290x; 1.1146x over previous
#include <cuda_runtime.h>
#include <cuda_fp16.h>
#include <math.h>
#include <stdint.h>

#define Bn   2
#define Sn   4096
#define Hn   1024
#define Mn   (Bn * Sn)       // 8192 rows
#define WIN  32

// ---------------- scratch (no allocations allowed) ----------------
__device__ uint32_t g_x_h   [Mn * Hn / 2];
__device__ uint32_t g_wqkv_h[3 * Hn * Hn / 2];   // rows: [Wq | Wk | Wv]
__device__ uint32_t g_wo_h  [Hn * Hn / 2];
__device__ uint32_t g_w1_h  [(Hn / 2) * Hn / 2];
__device__ uint32_t g_w2_h  [Hn * (Hn / 2) / 2];
__device__ uint32_t g_qkv_h [Mn * 3 * Hn / 2];   // per row: [q(512u32) | k(512) | v(512)]
__device__ uint32_t g_at_h  [Mn * Hn / 2];
__device__ uint32_t g_dr_h  [Mn * Hn / 2];       // draft, fp16 pairs
__device__ uint32_t g_ln_h  [Mn * Hn / 2];
__device__ uint32_t g_h1_h  [Mn * Hn / 4];

#define QKV_LD (3 * Hn / 2)   // 1536 u32 per row
#define KOFF   (Hn / 2)       // 512
#define VOFF   (Hn)           // 1024

// ---------------- fp16 helpers ----------------
__device__ __forceinline__ uint32_t pack2_h(__half a, __half b) {
    __half2 t; t.x = a; t.y = b;
    return *(uint32_t*)&t;
}
__device__ __forceinline__ uint32_t hi2h(float x, float y) {
    return pack2_h(__float2half_rn(x), __float2half_rn(y));
}
__device__ __forceinline__ float2 h2f2(uint32_t u) {
    __half2 h = *(__half2*)&u;
    return __half22float2(h);
}
__device__ __forceinline__ void mma_f16(float c[4], const uint32_t a[4], uint32_t b0, uint32_t b1) {
    asm("mma.sync.aligned.m16n8k16.row.col.f32.f16.f16.f32 "
        "{%0,%1,%2,%3}, {%4,%5,%6,%7}, {%8,%9}, {%0,%1,%2,%3};\n"
        : "+f"(c[0]), "+f"(c[1]), "+f"(c[2]), "+f"(c[3])
        : "r"(a[0]), "r"(a[1]), "r"(a[2]), "r"(a[3]), "r"(b0), "r"(b1));
}
__device__ __forceinline__ void ldmx4(uint32_t r[4], const uint32_t* p) {
    uint32_t a = (uint32_t)__cvta_generic_to_shared(p);
    asm volatile("ldmatrix.sync.aligned.m8n8.x4.shared.b16 {%0,%1,%2,%3}, [%4];"
        : "=r"(r[0]), "=r"(r[1]), "=r"(r[2]), "=r"(r[3]) : "r"(a));
}
__device__ __forceinline__ void ldmx2t(uint32_t r[2], const uint32_t* p) {
    uint32_t a = (uint32_t)__cvta_generic_to_shared(p);
    asm volatile("ldmatrix.sync.aligned.m8n8.x2.trans.shared.b16 {%0,%1}, [%2];"
        : "=r"(r[0]), "=r"(r[1]) : "r"(a));
}
__device__ __forceinline__ void cp16(uint32_t sdst, const void* gsrc) {
    asm volatile("cp.async.cg.shared.global [%0], [%1], 16;" :: "r"(sdst), "l"(gsrc));
}
#define CP_COMMIT() asm volatile("cp.async.commit_group;" ::: "memory")

// ---------------- fused conversion ----------------
__global__ __launch_bounds__(256) void conv_all(
    const float* s0, uint32_t* d0, int n0,
    const float* s1, uint32_t* d1, int n1,
    const float* s2, uint32_t* d2, int n2,
    const float* s3, uint32_t* d3, int n3,
    const float* s4, uint32_t* d4, int n4c,
    const float* s5, uint32_t* d5, int n5,
    const float* s6, uint32_t* d6, int n6)
{
    int i = blockIdx.x * 256 + threadIdx.x;
    const float* s; uint32_t* d;
    if      (i < n0)                        { s = s0; d = d0; }
    else if ((i -= n0) < n1)                { s = s1; d = d1; }
    else if ((i -= n1) < n2)                { s = s2; d = d2; }
    else if ((i -= n2) < n3)                { s = s3; d = d3; }
    else if ((i -= n3) < n4c)               { s = s4; d = d4; }
    else if ((i -= n4c) < n5)               { s = s5; d = d5; }
    else if ((i -= n5) < n6)                { s = s6; d = d6; }
    else return;
    float4 v = ((const float4*)s)[i];
    ((uint2*)d)[i] = make_uint2(hi2h(v.x, v.y), hi2h(v.z, v.w));
}

// ---------------- GEMM (unchanged from R16) ----------------
#define BM 128
#define BN 128
#define SLD 20
#define MATW (BM * SLD)
#define STGW (2 * MATW)
#define NSTAGE 3
#define GEMM_SMEM (NSTAGE * STGW * 4)

template<int EPI>
__global__ __launch_bounds__(256, 2) void gemm_mma(
    const uint32_t* __restrict__ Ahg, const uint32_t* __restrict__ Bhg,
    float* __restrict__ C, uint32_t* __restrict__ Chi,
    int M, int N, int K,
    const float* __restrict__ aux1, const float* __restrict__ aux2,
    const uint32_t* __restrict__ aux1h)
{
    extern __shared__ uint32_t smem[];

    const int Kd2  = K >> 1;
    const int nt   = Kd2 >> 4;
    const int tid  = threadIdx.x;
    const int wid  = tid >> 5;
    const int lane = tid & 31;
    const int g    = lane >> 2;
    const int tq   = lane & 3;

    const int bm = blockIdx.y * BM;
    const int bn = blockIdx.x * BN;
    const int m0 = (wid & 3) * 32;
    const int n0 = (wid >> 2) * 64;

    const int sr0 = tid >> 2,         sc0 = (tid & 3) << 2;
    const int sr1 = (tid + 256) >> 2, sc1 = ((tid + 256) & 3) << 2;
    const uint32_t smem_base = (uint32_t)__cvta_generic_to_shared(smem);

    float acc[2][8][4];
#pragma unroll
    for (int i = 0; i < 2; i++)
#pragma unroll
        for (int j = 0; j < 8; j++)
#pragma unroll
            for (int r = 0; r < 4; r++) acc[i][j][r] = 0.f;

    const int ar  = m0 + ((lane & 15) >> 3) * 8 + (lane & 7);
    const int ac4 = (lane >> 4) * 4;
    const int br  = n0 + (lane >> 4) * 8 + (lane & 7);
    const int bc4 = ((lane & 15) >> 3) * 4;

    auto stage = [&](int k, int b) {
        const uint32_t sbase = smem_base + (uint32_t)(b * STGW) * 4u;
        const int koff = k * 16;
        {
            const size_t ga = (size_t)(bm + sr0) * Kd2 + koff + sc0;
            const size_t gb = (size_t)(bn + sr0) * Kd2 + koff + sc0;
            const uint32_t so = (uint32_t)(sr0 * SLD + sc0) * 4u;
            cp16(sbase + 0 * MATW * 4 + so, Ahg + ga);
            cp16(sbase + 1 * MATW * 4 + so, Bhg + gb);
        }
        {
            const size_t ga = (size_t)(bm + sr1) * Kd2 + koff + sc1;
            const size_t gb = (size_t)(bn + sr1) * Kd2 + koff + sc1;
            const uint32_t so = (uint32_t)(sr1 * SLD + sc1) * 4u;
            cp16(sbase + 0 * MATW * 4 + so, Ahg + ga);
            cp16(sbase + 1 * MATW * 4 + so, Bhg + gb);
        }
    };

    stage(0, 0);
    CP_COMMIT();
    if (nt > 1) { stage(1, 1); CP_COMMIT(); }

    int b = 0;
    for (int k = 0; k < nt; k++) {
        if (k + 2 < nt) {
            int bs = b + 2; if (bs >= NSTAGE) bs -= NSTAGE;
            stage(k + 2, bs);
            CP_COMMIT();
            asm volatile("cp.async.wait_group 2;" ::: "memory");
        } else if (k + 1 < nt) {
            asm volatile("cp.async.wait_group 1;" ::: "memory");
        } else {
            asm volatile("cp.async.wait_group 0;" ::: "memory");
        }
        __syncthreads();

        const uint32_t* sAh = smem + b * STGW + 0 * MATW;
        const uint32_t* sBh = smem + b * STGW + 1 * MATW;

#pragma unroll
        for (int kc = 0; kc < 16; kc += 8) {
            uint32_t ah[2][4];
            ldmx4(ah[0], sAh + (ar     ) * SLD + kc + ac4);
            ldmx4(ah[1], sAh + (ar + 16) * SLD + kc + ac4);
#pragma unroll
            for (int h = 0; h < 2; h++) {
                uint32_t bh0[4], bh1[4];
                ldmx4(bh0, sBh + (br + (2 * h)     * 16) * SLD + kc + bc4);
                ldmx4(bh1, sBh + (br + (2 * h + 1) * 16) * SLD + kc + bc4);
                const int p0 = 4 * h, p1 = 4 * h + 2;
                mma_f16(acc[0][p0],     ah[0], bh0[0], bh0[1]);
                mma_f16(acc[0][p0 + 1], ah[0], bh0[2], bh0[3]);
                mma_f16(acc[1][p0],     ah[1], bh0[0], bh0[1]);
                mma_f16(acc[1][p0 + 1], ah[1], bh0[2], bh0[3]);
                mma_f16(acc[0][p1],     ah[0], bh1[0], bh1[1]);
                mma_f16(acc[0][p1 + 1], ah[0], bh1[2], bh1[3]);
                mma_f16(acc[1][p1],     ah[1], bh1[0], bh1[1]);
                mma_f16(acc[1][p1 + 1], ah[1], bh1[2], bh1[3]);
            }
        }
        __syncthreads();
        if (++b >= NSTAGE) b = 0;
    }

#pragma unroll
    for (int mf = 0; mf < 2; mf++) {
#pragma unroll
        for (int nf = 0; nf < 8; nf++) {
            const int r0 = bm + m0 + mf * 16 + g;
            const int r1 = r0 + 8;
            const int cc = bn + n0 + nf * 8 + tq * 2;
            const int Nd2 = N >> 1;
            float v0 = acc[mf][nf][0], v1 = acc[mf][nf][1];
            float v2 = acc[mf][nf][2], v3 = acc[mf][nf][3];

            if (EPI == 5) {
                const float2 a0 = *(const float2*)(aux1 + (size_t)r0 * N + cc);
                const float2 a1 = *(const float2*)(aux1 + (size_t)r1 * N + cc);
                v0 += a0.x; v1 += a0.y; v2 += a1.x; v3 += a1.y;
            }
            if (EPI == 6) {
                const float2 a0 = h2f2(aux1h[(size_t)r0 * Nd2 + (cc >> 1)]);
                const float2 a1 = h2f2(aux1h[(size_t)r1 * Nd2 + (cc >> 1)]);
                v0 += a0.x; v1 += a0.y; v2 += a1.x; v3 += a1.y;
            }
            if (EPI == 2 || EPI == 6) {
                const float2 bb = *(const float2*)(aux2 + cc);
                v0 += bb.x; v1 += bb.y; v2 += bb.x; v3 += bb.y;
            }
            if (EPI == 2) {
                v0 *= normcdff(v0); v1 *= normcdff(v1);
                v2 *= normcdff(v2); v3 *= normcdff(v3);
            }
            if (EPI == 2 || EPI == 4 || EPI == 5) {
                Chi[(size_t)r0 * Nd2 + (cc >> 1)] = hi2h(v0, v1);
                Chi[(size_t)r1 * Nd2 + (cc >> 1)] = hi2h(v2, v3);
            } else {
                *(float2*)(C + (size_t)r0 * N + cc) = make_float2(v0, v1);
                *(float2*)(C + (size_t)r1 * N + cc) = make_float2(v2, v3);
            }
        }
    }
}

// ---------------- fused banded attention: mma scores + softmax + mma PV ----------------
// One block = 32 queries. S[32,64] (r = ti + w), softmax -> P fp16, O = P @ V.
// smem (u32): Kbuf[2][64][36] @0, Qbuf[2][32][36] @4608 (phase A)
//             Vbuf[2][64][68] @0 (phase B, aliases), Sf float[32][66] @8704, P[32][36] @10816
__global__ __launch_bounds__(256) void attn_fused(
    const uint32_t* __restrict__ qkv, uint32_t* __restrict__ Ohi)
{
    __shared__ uint32_t sm[11968];

    const int tid  = threadIdx.x;
    const int wid  = tid >> 5;
    const int lane = tid & 31;
    const int g    = lane >> 2;
    const int tq   = lane & 3;
    const int q0   = blockIdx.x * 32;
    const int bSn  = blockIdx.y * Sn;
    const uint32_t smb = (uint32_t)__cvta_generic_to_shared(sm);

    // warp tiling (both phases): m0 = 16-query tile, n016 = 16-wide n tile
    const int m0   = (wid & 1) * 16;
    const int n016 = (wid >> 1) * 16;
    const int ar   = m0 + ((lane & 15) >> 3) * 8 + (lane & 7);
    const int ac4  = (lane >> 4) * 4;
    const int brr  = n016 + (lane >> 4) * 8 + (lane & 7);
    const int bc4  = ((lane & 15) >> 3) * 4;

    float*    Sf = (float*)(sm + 8704);
    uint32_t* Pp = sm + 10816;

    // ---- zero boundary K rows (both buffers) ----
    if (q0 == 0) {
        for (int i = tid; i < 31 * 36; i += 256) { sm[i] = 0u; sm[2304 + i] = 0u; }
    }
    for (int i = tid; i < 36; i += 256) { sm[63 * 36 + i] = 0u; sm[2304 + 63 * 36 + i] = 0u; }

    auto fillA = [&](int ci, int buf) {
        const int h0u = ci * 32;
        const uint32_t kb = smb + (uint32_t)(buf * 2304) * 4u;
        const uint32_t qb = smb + (uint32_t)(4608 + buf * 1152) * 4u;
        for (int idx = tid; idx < 63 * 8; idx += 256) {
            const int r = idx >> 3, c4 = (idx & 7) << 2;
            const int jb = q0 - 31 + r;
            if (jb >= 0)
                cp16(kb + (uint32_t)(r * 36 + c4) * 4u,
                     qkv + (size_t)(bSn + jb) * QKV_LD + KOFF + h0u + c4);
        }
        for (int idx = tid; idx < 32 * 8; idx += 256) {
            const int r = idx >> 3, c4 = (idx & 7) << 2;
            cp16(qb + (uint32_t)(r * 36 + c4) * 4u,
                 qkv + (size_t)(bSn + q0 + r) * QKV_LD + h0u + c4);
        }
    };

    float accS[2][4];
#pragma unroll
    for (int i = 0; i < 2; i++)
#pragma unroll
        for (int j = 0; j < 4; j++) accS[i][j] = 0.f;

    fillA(0, 0);
    CP_COMMIT();

    for (int ci = 0; ci < 16; ci++) {
        const int buf = ci & 1;
        if (ci + 1 < 16) {
            fillA(ci + 1, buf ^ 1);
            CP_COMMIT();
            asm volatile("cp.async.wait_group 1;" ::: "memory");
        } else {
            asm volatile("cp.async.wait_group 0;" ::: "memory");
        }
        __syncthreads();

        const uint32_t* kb = sm + buf * 2304;
        const uint32_t* qb = sm + 4608 + buf * 1152;
#pragma unroll
        for (int kc = 0; kc < 32; kc += 8) {
            uint32_t ah[4], bh[4];
            ldmx4(ah, qb + ar * 36 + kc + ac4);
            ldmx4(bh, kb + brr * 36 + kc + bc4);
            mma_f16(accS[0], ah, bh[0], bh[1]);
            mma_f16(accS[1], ah, bh[2], bh[3]);
        }
        __syncthreads();
    }

    // ---- write S to smem ----
#pragma unroll
    for (int nf = 0; nf < 2; nf++) {
        const int col = n016 + nf * 8 + tq * 2;
        Sf[(m0 + g) * 66 + col]         = accS[nf][0];
        Sf[(m0 + g) * 66 + col + 1]     = accS[nf][1];
        Sf[(m0 + g + 8) * 66 + col]     = accS[nf][2];
        Sf[(m0 + g + 8) * 66 + col + 1] = accS[nf][3];
    }
    __syncthreads();

    // ---- softmax: warp w handles queries 4w..4w+3; lane owns r = 2*lane, 2*lane+1 ----
#pragma unroll
    for (int qq = 0; qq < 4; qq++) {
        const int q  = wid * 4 + qq;
        const int lo = max(q, 31 - q0);
        const int r0v = 2 * lane, r1v = r0v + 1;
        const bool v0 = (r0v >= lo) && (r0v <= q + 31);
        const bool v1 = (r1v >= lo) && (r1v <= q + 31);
        float s0 = v0 ? Sf[q * 66 + r0v] * (1.0f / 32.0f) : -1e30f;
        float s1 = v1 ? Sf[q * 66 + r1v] * (1.0f / 32.0f) : -1e30f;
        float m = fmaxf(s0, s1);
#pragma unroll
        for (int o = 16; o; o >>= 1) m = fmaxf(m, __shfl_xor_sync(0xffffffffu, m, o));
        float p0 = v0 ? expf(s0 - m) : 0.f;
        float p1 = v1 ? expf(s1 - m) : 0.f;
        float sum = p0 + p1;
#pragma unroll
        for (int o = 16; o; o >>= 1) sum += __shfl_xor_sync(0xffffffffu, sum, o);
        const float inv = 1.0f / sum;
        Pp[q * 36 + lane] = hi2h(p0 * inv, p1 * inv);
    }
    __syncthreads();

    // ---- phase B: O = P @ V ----
    // hoist P fragments (A operand): 4 k-steps over r=64
    uint32_t aP[4][4];
#pragma unroll
    for (int ks = 0; ks < 4; ks++)
        ldmx4(aP[ks], Pp + ar * 36 + ks * 8 + ac4);

    // zero boundary V rows (both buffers; aliases Kbuf region)
    if (q0 == 0) {
        for (int i = tid; i < 31 * 68; i += 256) { sm[i] = 0u; sm[4352 + i] = 0u; }
    }
    for (int i = tid; i < 68; i += 256) { sm[63 * 68 + i] = 0u; sm[4352 + 63 * 68 + i] = 0u; }
    __syncthreads();

    auto fillV = [&](int ci, int buf) {
        const int h0u = ci * 64;
        const uint32_t vb = smb + (uint32_t)(buf * 4352) * 4u;
        for (int idx = tid; idx < 63 * 16; idx += 256) {
            const int r = idx >> 4, c4 = (idx & 15) << 2;
            const int jb = q0 - 31 + r;
            if (jb >= 0)
                cp16(vb + (uint32_t)(r * 68 + c4) * 4u,
                     qkv + (size_t)(bSn + jb) * QKV_LD + VOFF + h0u + c4);
        }
    };

    fillV(0, 0);
    CP_COMMIT();

    const int hb4  = (wid >> 1) * 16;                 // u32 offset of warp's 32-half tile
    const int vrl  = (lane & 7) + ((lane >> 3) & 1) * 8;   // lane row within 16

    for (int ci = 0; ci < 8; ci++) {
        const int buf = ci & 1;
        if (ci + 1 < 8) {
            fillV(ci + 1, buf ^ 1);
            CP_COMMIT();
            asm volatile("cp.async.wait_group 1;" ::: "memory");
        } else {
            asm volatile("cp.async.wait_group 0;" ::: "memory");
        }
        __syncthreads();

        const uint32_t* vb = sm + buf * 4352;
        float accO[4][4];
#pragma unroll
        for (int i = 0; i < 4; i++)
#pragma unroll
            for (int j = 0; j < 4; j++) accO[i][j] = 0.f;

#pragma unroll
        for (int ks = 0; ks < 4; ks++) {
            const uint32_t* vrow = vb + (ks * 16 + vrl) * 68 + hb4;
#pragma unroll
            for (int nt = 0; nt < 4; nt++) {
                uint32_t bb[2];
                ldmx2t(bb, vrow + nt * 4);
                mma_f16(accO[nt], aP[ks], bb[0], bb[1]);
            }
        }

        const size_t rb0 = (size_t)(bSn + q0 + m0 + g) * (Hn / 2) + ci * 64 + hb4 + tq;
#pragma unroll
        for (int nt = 0; nt < 4; nt++) {
            Ohi[rb0 + nt * 4]                  = hi2h(accO[nt][0], accO[nt][1]);
            Ohi[rb0 + nt * 4 + 8 * (Hn / 2)]   = hi2h(accO[nt][2], accO[nt][3]);
        }
        __syncthreads();
    }
}

// ---------------- layernorm: single-pass, fp16 in/out ----------------
__global__ __launch_bounds__(256) void ln_kernel(
    const uint32_t* __restrict__ Xh, const float* __restrict__ w,
    const float* __restrict__ bb, uint32_t* __restrict__ Yhi)
{
    const int row = blockIdx.x;
    const int tid = threadIdx.x;
    const uint2 u = *(const uint2*)(Xh + (size_t)row * (Hn / 2) + tid * 2);
    const float2 f0 = h2f2(u.x), f1 = h2f2(u.y);

    float s  = f0.x + f0.y + f1.x + f1.y;
    float ss = f0.x * f0.x + f0.y * f0.y + f1.x * f1.x + f1.y * f1.y;

    __shared__ float red[64];
#pragma unroll
    for (int o = 16; o; o >>= 1) {
        s  += __shfl_down_sync(0xffffffffu, s,  o);
        ss += __shfl_down_sync(0xffffffffu, ss, o);
    }
    const int warp = tid >> 5, lane = tid & 31;
    if (lane == 0) { red[warp] = s; red[32 + warp] = ss; }
    __syncthreads();
    if (tid == 0) {
        float S = 0.f, SS = 0.f;
        for (int i = 0; i < 8; i++) { S += red[i]; SS += red[32 + i]; }
        red[0] = S; red[1] = SS;
    }
    __syncthreads();
    const float mu   = red[0] * (1.0f / Hn);
    const float var  = red[1] * (1.0f / Hn) - mu * mu;
    const float rstd = rsqrtf(var + 1e-5f);

    const float4 wv = *(const float4*)(w  + tid * 4);
    const float4 bv = *(const float4*)(bb + tid * 4);
    float y0 = (f0.x - mu) * rstd * wv.x + bv.x;
    float y1 = (f0.y - mu) * rstd * wv.y + bv.y;
    float y2 = (f1.x - mu) * rstd * wv.z + bv.z;
    float y3 = (f1.y - mu) * rstd * wv.w + bv.w;
    *(uint2*)(Yhi + (size_t)row * (Hn / 2) + tid * 2) = make_uint2(hi2h(y0, y1), hi2h(y2, y3));
}

// ---------------- launch ----------------
extern "C" void kernel_launch(void* const* d_in, const int* in_sizes, int n_in,
                              void* d_out, int out_size)
{
    const float* x   = (const float*)d_in[0];
    const float* Wq  = (const float*)d_in[1];
    const float* Wk  = (const float*)d_in[2];
    const float* Wv  = (const float*)d_in[3];
    const float* Wo  = (const float*)d_in[4];
    const float* lnw = (const float*)d_in[5];
    const float* lnb = (const float*)d_in[6];
    const float* W1  = (const float*)d_in[7];
    const float* b1  = (const float*)d_in[8];
    const float* W2  = (const float*)d_in[9];
    const float* b2  = (const float*)d_in[10];
    float* out = (float*)d_out;

    uint32_t *xh, *wqkvh, *woh, *w1h, *w2h, *qkvh, *ath, *drh, *lnh, *h1h;
    cudaGetSymbolAddress((void**)&xh,    g_x_h);
    cudaGetSymbolAddress((void**)&wqkvh, g_wqkv_h);
    cudaGetSymbolAddress((void**)&woh,   g_wo_h);
    cudaGetSymbolAddress((void**)&w1h,   g_w1_h);
    cudaGetSymbolAddress((void**)&w2h,   g_w2_h);
    cudaGetSymbolAddress((void**)&qkvh,  g_qkv_h);
    cudaGetSymbolAddress((void**)&ath,   g_at_h);
    cudaGetSymbolAddress((void**)&drh,   g_dr_h);
    cudaGetSymbolAddress((void**)&lnh,   g_ln_h);
    cudaGetSymbolAddress((void**)&h1h,   g_h1_h);

    cudaFuncSetAttribute(gemm_mma<2>, cudaFuncAttributeMaxDynamicSharedMemorySize, GEMM_SMEM);
    cudaFuncSetAttribute(gemm_mma<4>, cudaFuncAttributeMaxDynamicSharedMemorySize, GEMM_SMEM);
    cudaFuncSetAttribute(gemm_mma<5>, cudaFuncAttributeMaxDynamicSharedMemorySize, GEMM_SMEM);
    cudaFuncSetAttribute(gemm_mma<6>, cudaFuncAttributeMaxDynamicSharedMemorySize, GEMM_SMEM);

    // fused conversion (one launch)
    const int nX = Mn * Hn / 4;
    const int nW = Hn * Hn / 4;
    const int nH = Hn * Hn / 8;
    const int total = nX + 4 * nW + 2 * nH;
    conv_all<<<(total + 255) / 256, 256>>>(
        x,  xh, nX,
        Wq, wqkvh,              nW,
        Wk, wqkvh + 1 * nW * 2, nW,
        Wv, wqkvh + 2 * nW * 2, nW,
        Wo, woh, nW,
        W1, w1h, nH,
        W2, w2h, nH);

    dim3 gridQKV(3 * Hn / BN,   Mn / BM);   // (24, 64)
    dim3 gridH  (Hn / BN,       Mn / BM);   // (8, 64)
    dim3 gridH2 ((Hn / 2) / BN, Mn / BM);   // (4, 64)

    // fused QKV projection -> packed fp16 [q|k|v] rows
    gemm_mma<4><<<gridQKV, 256, GEMM_SMEM>>>(xh, wqkvh, nullptr, qkvh, Mn, 3 * Hn, Hn, nullptr, nullptr, nullptr);

    // fused banded attention (mma scores + softmax + mma PV)
    attn_fused<<<dim3(Sn / 32, Bn), 256>>>(qkvh, ath);

    // draft = fp16(x + attn @ Wo^T)
    gemm_mma<5><<<gridH, 256, GEMM_SMEM>>>(ath, woh, nullptr, drh, Mn, Hn, Hn, x, nullptr, nullptr);

    // layernorm (fp16 in/out)
    ln_kernel<<<Mn, 256>>>(drh, lnw, lnb, lnh);

    // h1 = gelu(ln @ W1^T + b1) -> fp16 pairs
    gemm_mma<2><<<gridH2, 256, GEMM_SMEM>>>(lnh, w1h, nullptr, h1h, Mn, Hn / 2, Hn, nullptr, b1, nullptr);

    // out = draft(fp16) + h1 @ W2^T + b2  (fp32)
    gemm_mma<6><<<gridH, 256, GEMM_SMEM>>>(h1h, w2h, out, nullptr, Mn, Hn, Hn / 2, nullptr, b2, drh);
}